// round 3
// baseline (speedup 1.0000x reference)
#include <cuda_runtime.h>
#include <math.h>
#include <stdint.h>

#define DIMS 1024
#define HEAD 16
#define HD   64
#define CTX  2048
#define BATCH 2
#define MROWS (BATCH*CTX)          // 4096
#define OUT_ELEMS (MROWS*DIMS)
#define QK_ELEMS  ((size_t)BATCH*HEAD*CTX*CTX)

// ---- scratch ----
__device__ float g_q [MROWS*DIMS];
__device__ float g_k [MROWS*DIMS];
__device__ float g_v [MROWS*DIMS];
__device__ float g_wv[MROWS*DIMS];
__device__ float g_o1[MROWS*DIMS];
__device__ float g_qk_fallback[QK_ELEMS];

// ---- tf32 helpers ----
__device__ __forceinline__ uint32_t cvt_tf32(float x) {
    uint32_t r; asm("cvt.rna.tf32.f32 %0, %1;" : "=r"(r) : "f"(x)); return r;
}
__device__ __forceinline__ void split_tf32(float x, uint32_t& h, uint32_t& l) {
    h = cvt_tf32(x);
    l = cvt_tf32(x - __uint_as_float(h));
}
__device__ __forceinline__ void mma8(float c[4],
    uint32_t a0, uint32_t a1, uint32_t a2, uint32_t a3,
    uint32_t b0, uint32_t b1)
{
    asm volatile("mma.sync.aligned.m16n8k8.row.col.f32.tf32.tf32.f32 "
        "{%0,%1,%2,%3}, {%4,%5,%6,%7}, {%8,%9}, {%0,%1,%2,%3};"
        : "+f"(c[0]), "+f"(c[1]), "+f"(c[2]), "+f"(c[3])
        : "r"(a0), "r"(a1), "r"(a2), "r"(a3), "r"(b0), "r"(b1));
}

// ============================================================
// Projection / output GEMM: C[4096,1024] = A[4096,1024] @ B[1024,1024]^T + bias
// tile 128x64, 8 warps (4Mx2N), warp 32x32, BK=16, 3xTF32 split
// ============================================================
__global__ void __launch_bounds__(256) gemm_tc(
    const float* __restrict__ A, const float* __restrict__ B,
    const float* __restrict__ bias, float* __restrict__ C)
{
    __shared__ uint32_t Ah[16][132], Al[16][132];
    __shared__ uint32_t Bh[16][68],  Bl[16][68];

    int t = threadIdx.x, warp = t >> 5, lane = t & 31;
    int row0 = blockIdx.y * 128, col0 = blockIdx.x * 64;
    int wm = (warp >> 1) * 32, wn = (warp & 1) * 32;
    int gr = lane >> 2, gq = lane & 3;

    int ar = t >> 1, ac = (t & 1) * 8;
    int br = t >> 2, bc = (t & 3) * 4;
    const float* Ap = A + (size_t)(row0 + ar) * DIMS + ac;
    const float* Bp = B + (size_t)(col0 + br) * DIMS + bc;

    float acc[2][4][4] = {};

    float4 pa0 = *(const float4*)(Ap);
    float4 pa1 = *(const float4*)(Ap + 4);
    float4 pb0 = *(const float4*)(Bp);

    for (int k0 = 0; k0 < DIMS; k0 += 16) {
        float av[8] = {pa0.x,pa0.y,pa0.z,pa0.w, pa1.x,pa1.y,pa1.z,pa1.w};
        #pragma unroll
        for (int j = 0; j < 8; j++) split_tf32(av[j], Ah[ac+j][ar], Al[ac+j][ar]);
        float bvv[4] = {pb0.x,pb0.y,pb0.z,pb0.w};
        #pragma unroll
        for (int j = 0; j < 4; j++) split_tf32(bvv[j], Bh[bc+j][br], Bl[bc+j][br]);
        __syncthreads();
        if (k0 + 16 < DIMS) {
            pa0 = *(const float4*)(Ap + k0 + 16);
            pa1 = *(const float4*)(Ap + k0 + 20);
            pb0 = *(const float4*)(Bp + k0 + 16);
        }
        #pragma unroll
        for (int kk = 0; kk < 16; kk += 8) {
            uint32_t ah[2][4], al[2][4], bh[4][2], bl[4][2];
            #pragma unroll
            for (int ma = 0; ma < 2; ma++) {
                int r = wm + ma*16 + gr;
                ah[ma][0]=Ah[kk+gq][r];   ah[ma][1]=Ah[kk+gq][r+8];
                ah[ma][2]=Ah[kk+gq+4][r]; ah[ma][3]=Ah[kk+gq+4][r+8];
                al[ma][0]=Al[kk+gq][r];   al[ma][1]=Al[kk+gq][r+8];
                al[ma][2]=Al[kk+gq+4][r]; al[ma][3]=Al[kk+gq+4][r+8];
            }
            #pragma unroll
            for (int na = 0; na < 4; na++) {
                int cn = wn + na*8 + gr;
                bh[na][0]=Bh[kk+gq][cn]; bh[na][1]=Bh[kk+4+gq][cn];
                bl[na][0]=Bl[kk+gq][cn]; bl[na][1]=Bl[kk+4+gq][cn];
            }
            #pragma unroll
            for (int ma = 0; ma < 2; ma++)
                #pragma unroll
                for (int na = 0; na < 4; na++) {
                    mma8(acc[ma][na], ah[ma][0],ah[ma][1],ah[ma][2],ah[ma][3], bh[na][0],bh[na][1]);
                    mma8(acc[ma][na], ah[ma][0],ah[ma][1],ah[ma][2],ah[ma][3], bl[na][0],bl[na][1]);
                    mma8(acc[ma][na], al[ma][0],al[ma][1],al[ma][2],al[ma][3], bh[na][0],bh[na][1]);
                }
        }
        __syncthreads();
    }
    #pragma unroll
    for (int ma = 0; ma < 2; ma++)
        #pragma unroll
        for (int na = 0; na < 4; na++) {
            int r  = row0 + wm + ma*16 + gr;
            int cn = col0 + wn + na*8 + 2*gq;
            float b0 = bias ? bias[cn] : 0.f, b1 = bias ? bias[cn+1] : 0.f;
            float2 o0 = make_float2(acc[ma][na][0]+b0, acc[ma][na][1]+b1);
            float2 o1 = make_float2(acc[ma][na][2]+b0, acc[ma][na][3]+b1);
            *(float2*)(C + (size_t)r * DIMS + cn)     = o0;
            *(float2*)(C + (size_t)(r+8) * DIMS + cn) = o1;
        }
}

// ============================================================
// Logits: qk[bh,i,j] = S2 * (q_i.k_j) * gate(j); 128x64 tile, K=64, 3xTF32
// ============================================================
__global__ void __launch_bounds__(256) logits_tc(
    const float* __restrict__ q, const float* __restrict__ k,
    const float* __restrict__ factor, float* __restrict__ qk)
{
    __shared__ uint32_t Ah[16][132], Al[16][132];
    __shared__ uint32_t Bh[16][68],  Bl[16][68];
    __shared__ float zf[64];

    int t = threadIdx.x, warp = t >> 5, lane = t & 31;
    int bh = blockIdx.z, b = bh >> 4, h = bh & 15;
    int row0 = blockIdx.y * 128, col0 = blockIdx.x * 64;
    int wm = (warp >> 1) * 32, wn = (warp & 1) * 32;
    int gr = lane >> 2, gq = lane & 3;

    int ar = t >> 1, ac = (t & 1) * 8;
    int br = t >> 2, bc = (t & 3) * 4;
    const float* Ap = q + (size_t)(b*CTX + row0 + ar) * DIMS + h*HD + ac;
    const float* Bp = k + (size_t)(b*CTX + col0 + br) * DIMS + h*HD + bc;

    if (t < 64) {
        float kf = k[(size_t)(b*CTX + col0 + t) * DIMS + h*HD];
        float f = *factor;
        float zfac = fminf(fmaxf(log1pf(expf(f)), 0.f), 0.001f);
        zf[t] = (kf == 0.f) ? zfac : 1.f;
    }

    float acc[2][4][4] = {};
    float4 pa0 = *(const float4*)(Ap);
    float4 pa1 = *(const float4*)(Ap + 4);
    float4 pb0 = *(const float4*)(Bp);

    #pragma unroll
    for (int k0 = 0; k0 < HD; k0 += 16) {
        float av[8] = {pa0.x,pa0.y,pa0.z,pa0.w, pa1.x,pa1.y,pa1.z,pa1.w};
        #pragma unroll
        for (int j = 0; j < 8; j++) split_tf32(av[j], Ah[ac+j][ar], Al[ac+j][ar]);
        float bvv[4] = {pb0.x,pb0.y,pb0.z,pb0.w};
        #pragma unroll
        for (int j = 0; j < 4; j++) split_tf32(bvv[j], Bh[bc+j][br], Bl[bc+j][br]);
        __syncthreads();
        if (k0 + 16 < HD) {
            pa0 = *(const float4*)(Ap + k0 + 16);
            pa1 = *(const float4*)(Ap + k0 + 20);
            pb0 = *(const float4*)(Bp + k0 + 16);
        }
        #pragma unroll
        for (int kk = 0; kk < 16; kk += 8) {
            uint32_t ah[2][4], al[2][4], bh[4][2], bl[4][2];
            #pragma unroll
            for (int ma = 0; ma < 2; ma++) {
                int r = wm + ma*16 + gr;
                ah[ma][0]=Ah[kk+gq][r];   ah[ma][1]=Ah[kk+gq][r+8];
                ah[ma][2]=Ah[kk+gq+4][r]; ah[ma][3]=Ah[kk+gq+4][r+8];
                al[ma][0]=Al[kk+gq][r];   al[ma][1]=Al[kk+gq][r+8];
                al[ma][2]=Al[kk+gq+4][r]; al[ma][3]=Al[kk+gq+4][r+8];
            }
            #pragma unroll
            for (int na = 0; na < 4; na++) {
                int cn = wn + na*8 + gr;
                bh[na][0]=Bh[kk+gq][cn]; bh[na][1]=Bh[kk+4+gq][cn];
                bl[na][0]=Bl[kk+gq][cn]; bl[na][1]=Bl[kk+4+gq][cn];
            }
            #pragma unroll
            for (int ma = 0; ma < 2; ma++)
                #pragma unroll
                for (int na = 0; na < 4; na++) {
                    mma8(acc[ma][na], ah[ma][0],ah[ma][1],ah[ma][2],ah[ma][3], bh[na][0],bh[na][1]);
                    mma8(acc[ma][na], ah[ma][0],ah[ma][1],ah[ma][2],ah[ma][3], bl[na][0],bl[na][1]);
                    mma8(acc[ma][na], al[ma][0],al[ma][1],al[ma][2],al[ma][3], bh[na][0],bh[na][1]);
                }
        }
        __syncthreads();
    }
    const float S2 = 0.125f;  // (64^-0.25)^2
    float* Cb = qk + (size_t)bh * CTX * CTX;
    #pragma unroll
    for (int ma = 0; ma < 2; ma++)
        #pragma unroll
        for (int na = 0; na < 4; na++) {
            int r  = row0 + wm + ma*16 + gr;
            int cl = wn + na*8 + 2*gq;
            float z0 = zf[cl] * S2, z1 = zf[cl+1] * S2;
            float2 o0 = make_float2(acc[ma][na][0]*z0, acc[ma][na][1]*z1);
            float2 o1 = make_float2(acc[ma][na][2]*z0, acc[ma][na][3]*z1);
            *(float2*)(Cb + (size_t)r * CTX + col0 + cl)     = o0;
            *(float2*)(Cb + (size_t)(r+8) * CTX + col0 + cl) = o1;
        }
}

// ============================================================
// Online-softmax + AV via mma: 128 q-rows x 64 d per block, key chunks of 32
// P in tf32 (single), V split (2 mmas)
// ============================================================
__global__ void __launch_bounds__(256) av_tc(
    const float* __restrict__ qkbuf, const float* __restrict__ v,
    float* __restrict__ wv)
{
    __shared__ uint32_t Ps[32][132];
    __shared__ uint32_t Vh[32][68], Vl[32][68];
    __shared__ float redmax[128][2], redsum[128][2];
    __shared__ float mrow[128], rsum[128], rscale[128], rinv[128];

    int t = threadIdx.x, warp = t >> 5, lane = t & 31;
    int bh = blockIdx.y, b = bh >> 4, h = bh & 15;
    int row0 = blockIdx.x * 128;
    int wm = (warp >> 1) * 32, wn = (warp & 1) * 32;
    int gr = lane >> 2, gq = lane & 3;
    const float* L = qkbuf + (size_t)bh * CTX * CTX;

    int lrow = t >> 1, lhalf = t & 1, lseg = lhalf * 16;
    int vr = t >> 3, vc = (t & 7) * 8;

    if (t < 128) { mrow[t] = -3.0e38f; rsum[t] = 0.f; redsum[t][0] = 0.f; redsum[t][1] = 0.f; }
    __syncthreads();

    float acc[2][4][4] = {};

    for (int kc = 0; kc < CTX; kc += 32) {
        const float* Lp = L + (size_t)(row0 + lrow) * CTX + kc + lseg;
        float4 x0 = *(const float4*)(Lp);
        float4 x1 = *(const float4*)(Lp + 4);
        float4 x2 = *(const float4*)(Lp + 8);
        float4 x3 = *(const float4*)(Lp + 12);
        float lm = fmaxf(
            fmaxf(fmaxf(fmaxf(x0.x,x0.y),fmaxf(x0.z,x0.w)), fmaxf(fmaxf(x1.x,x1.y),fmaxf(x1.z,x1.w))),
            fmaxf(fmaxf(fmaxf(x2.x,x2.y),fmaxf(x2.z,x2.w)), fmaxf(fmaxf(x3.x,x3.y),fmaxf(x3.z,x3.w))));
        redmax[lrow][lhalf] = lm;

        const float* Vp = v + (size_t)(b*CTX + kc + vr) * DIMS + h*HD + vc;
        float4 v0 = *(const float4*)(Vp);
        float4 v1 = *(const float4*)(Vp + 4);
        float vv[8] = {v0.x,v0.y,v0.z,v0.w, v1.x,v1.y,v1.z,v1.w};
        #pragma unroll
        for (int j = 0; j < 8; j++) split_tf32(vv[j], Vh[vr][vc+j], Vl[vr][vc+j]);
        __syncthreads();

        if (t < 128) {
            float cm = fmaxf(redmax[t][0], redmax[t][1]);
            float mo = mrow[t], mn = fmaxf(mo, cm);
            float sc = __expf(mo - mn);
            mrow[t] = mn; rscale[t] = sc;
            rsum[t] = (rsum[t] + redsum[t][0] + redsum[t][1]) * sc;
        }
        __syncthreads();

        float mr = mrow[lrow];
        float xs[16] = {x0.x,x0.y,x0.z,x0.w, x1.x,x1.y,x1.z,x1.w,
                        x2.x,x2.y,x2.z,x2.w, x3.x,x3.y,x3.z,x3.w};
        float ps = 0.f;
        #pragma unroll
        for (int j = 0; j < 16; j++) {
            float e = __expf(xs[j] - mr);
            ps += e;
            Ps[lseg + j][lrow] = cvt_tf32(e);
        }
        redsum[lrow][lhalf] = ps;

        // rescale accumulators
        #pragma unroll
        for (int ma = 0; ma < 2; ma++) {
            float s0 = rscale[wm + ma*16 + gr];
            float s1 = rscale[wm + ma*16 + gr + 8];
            #pragma unroll
            for (int na = 0; na < 4; na++) {
                acc[ma][na][0] *= s0; acc[ma][na][1] *= s0;
                acc[ma][na][2] *= s1; acc[ma][na][3] *= s1;
            }
        }
        __syncthreads();

        #pragma unroll
        for (int kk = 0; kk < 32; kk += 8) {
            uint32_t ap[2][4], bh2[4][2], bl2[4][2];
            #pragma unroll
            for (int ma = 0; ma < 2; ma++) {
                int r = wm + ma*16 + gr;
                ap[ma][0]=Ps[kk+gq][r];   ap[ma][1]=Ps[kk+gq][r+8];
                ap[ma][2]=Ps[kk+gq+4][r]; ap[ma][3]=Ps[kk+gq+4][r+8];
            }
            #pragma unroll
            for (int na = 0; na < 4; na++) {
                int cn = wn + na*8 + gr;
                bh2[na][0]=Vh[kk+gq][cn]; bh2[na][1]=Vh[kk+4+gq][cn];
                bl2[na][0]=Vl[kk+gq][cn]; bl2[na][1]=Vl[kk+4+gq][cn];
            }
            #pragma unroll
            for (int ma = 0; ma < 2; ma++)
                #pragma unroll
                for (int na = 0; na < 4; na++) {
                    mma8(acc[ma][na], ap[ma][0],ap[ma][1],ap[ma][2],ap[ma][3], bh2[na][0],bh2[na][1]);
                    mma8(acc[ma][na], ap[ma][0],ap[ma][1],ap[ma][2],ap[ma][3], bl2[na][0],bl2[na][1]);
                }
        }
        __syncthreads();
    }

    if (t < 128) rinv[t] = 1.f / (rsum[t] + redsum[t][0] + redsum[t][1]);
    __syncthreads();

    #pragma unroll
    for (int ma = 0; ma < 2; ma++)
        #pragma unroll
        for (int na = 0; na < 4; na++) {
            int rl = wm + ma*16 + gr;
            int r  = row0 + rl;
            int cn = h*HD + wn + na*8 + 2*gq;
            float i0 = rinv[rl], i1 = rinv[rl + 8];
            float2 o0 = make_float2(acc[ma][na][0]*i0, acc[ma][na][1]*i0);
            float2 o1 = make_float2(acc[ma][na][2]*i1, acc[ma][na][3]*i1);
            *(float2*)(wv + (size_t)(b*CTX + r) * DIMS + cn)     = o0;
            *(float2*)(wv + (size_t)(b*CTX + r + 8) * DIMS + cn) = o1;
        }
}

// Vh/Vl note: Ps/Vh/Vl are written as [k][m]/[k][n]; V loader writes rows (keys).
// Fix: loader writes Vh[vr][vc+j] where vr=key row — consistent with B-frag reads Vh[k][n]. OK.

// ============================================================
extern "C" void kernel_launch(void* const* d_in, const int* in_sizes, int n_in,
                              void* d_out, int out_size)
{
    const float* x    = (const float*)d_in[0];
    const float* Wq   = (const float*)d_in[1];
    const float* bq   = (const float*)d_in[2];
    const float* Wk   = (const float*)d_in[3];
    const float* Wv   = (const float*)d_in[4];
    const float* bv   = (const float*)d_in[5];
    const float* Wout = (const float*)d_in[6];
    const float* bout = (const float*)d_in[7];
    const float* factor = (const float*)d_in[8];

    float *qp, *kp, *vp, *wvp, *o1p, *qkfb;
    cudaGetSymbolAddress((void**)&qp,  g_q);
    cudaGetSymbolAddress((void**)&kp,  g_k);
    cudaGetSymbolAddress((void**)&vp,  g_v);
    cudaGetSymbolAddress((void**)&wvp, g_wv);
    cudaGetSymbolAddress((void**)&o1p, g_o1);
    cudaGetSymbolAddress((void**)&qkfb, g_qk_fallback);

    float* out = (float*)d_out;
    float* qkdst = ((size_t)out_size >= (size_t)OUT_ELEMS + QK_ELEMS)
                 ? (out + OUT_ELEMS) : qkfb;

    dim3 gp(DIMS/64, MROWS/128);           // (16, 32)
    gemm_tc<<<gp, 256>>>(x, Wq, bq,      qp);
    gemm_tc<<<gp, 256>>>(x, Wk, nullptr, kp);
    gemm_tc<<<gp, 256>>>(x, Wv, bv,      vp);

    dim3 gl(CTX/64, CTX/128, BATCH*HEAD);  // (32, 16, 32)
    logits_tc<<<gl, 256>>>(qp, kp, factor, qkdst);

    dim3 ga(CTX/128, BATCH*HEAD);          // (16, 32)
    av_tc<<<ga, 256>>>(qkdst, vp, wvp);

    gemm_tc<<<gp, 256>>>(wvp, Wout, bout, o1p);
    gemm_tc<<<gp, 256>>>(o1p, Wout, bout, out);
}

// round 4
// speedup vs baseline: 2.0134x; 2.0134x over previous
#include <cuda_runtime.h>
#include <cuda_bf16.h>
#include <math.h>
#include <stdint.h>

#define DIMS 1024
#define HEAD 16
#define HD   64
#define CTX  2048
#define BATCH 2
#define MROWS (BATCH*CTX)
#define OUT_ELEMS (MROWS*DIMS)
#define QK_ELEMS  ((size_t)BATCH*HEAD*CTX*CTX)

// ---- scratch ----
__device__ float g_q [MROWS*DIMS];
__device__ float g_k [MROWS*DIMS];
__device__ float g_v [MROWS*DIMS];
__device__ float g_wv[MROWS*DIMS];
__device__ float g_w2[DIMS*DIMS];
__device__ float g_b2[DIMS];
__device__ float g_qk_fallback[QK_ELEMS];

// ---- helpers ----
__device__ __forceinline__ uint32_t smaddr(const void* p){
    return (uint32_t)__cvta_generic_to_shared(p);
}
__device__ __forceinline__ void ldsm4(uint32_t&r0,uint32_t&r1,uint32_t&r2,uint32_t&r3,uint32_t a){
    asm volatile("ldmatrix.sync.aligned.m8n8.x4.shared.b16 {%0,%1,%2,%3},[%4];"
        :"=r"(r0),"=r"(r1),"=r"(r2),"=r"(r3):"r"(a));
}
__device__ __forceinline__ void ldsm4t(uint32_t&r0,uint32_t&r1,uint32_t&r2,uint32_t&r3,uint32_t a){
    asm volatile("ldmatrix.sync.aligned.m8n8.x4.trans.shared.b16 {%0,%1,%2,%3},[%4];"
        :"=r"(r0),"=r"(r1),"=r"(r2),"=r"(r3):"r"(a));
}
__device__ __forceinline__ void mmabf(float c[4],
    uint32_t a0,uint32_t a1,uint32_t a2,uint32_t a3,uint32_t b0,uint32_t b1){
    asm volatile("mma.sync.aligned.m16n8k16.row.col.f32.bf16.bf16.f32 "
        "{%0,%1,%2,%3},{%4,%5,%6,%7},{%8,%9},{%0,%1,%2,%3};"
        :"+f"(c[0]),"+f"(c[1]),"+f"(c[2]),"+f"(c[3])
        :"r"(a0),"r"(a1),"r"(a2),"r"(a3),"r"(b0),"r"(b1));
}
__device__ __forceinline__ uint32_t packbf(float x, float y){
    __nv_bfloat162 t = __floats2bfloat162_rn(x,y);
    return *reinterpret_cast<uint32_t*>(&t);
}
__device__ __forceinline__ void split8(const float* x, uint4 &H, uint4 &L){
    float h[8], l[8];
    #pragma unroll
    for(int i=0;i<8;i++){
        __nv_bfloat16 hb = __float2bfloat16(x[i]);
        h[i] = __bfloat162float(hb);
        l[i] = x[i] - h[i];
    }
    H = make_uint4(packbf(h[0],h[1]),packbf(h[2],h[3]),packbf(h[4],h[5]),packbf(h[6],h[7]));
    L = make_uint4(packbf(l[0],l[1]),packbf(l[2],l[3]),packbf(l[4],l[5]),packbf(l[6],l[7]));
}
// fragment address generators
template<int S>
__device__ __forceinline__ uint32_t a_addr(uint32_t base, int r0, int k0, int lane){
    int r = r0 + (lane&7) + ((lane>>3)&1)*8;
    int k = k0 + ((lane>>4)&1)*8;
    return base + (uint32_t)(r*S + k)*2;
}
template<int S>
__device__ __forceinline__ uint32_t b_addr(uint32_t base, int n0, int k0, int lane){
    int n = n0 + (lane&7) + ((lane>>4)&1)*8;
    int k = k0 + ((lane>>3)&1)*8;
    return base + (uint32_t)(n*S + k)*2;
}
template<int S>
__device__ __forceinline__ uint32_t bt_addr(uint32_t base, int n0, int k0, int lane){
    int k = k0 + (lane&7) + ((lane>>3)&1)*8;
    int n = n0 + ((lane>>4)&1)*8;
    return base + (uint32_t)(k*S + n)*2;
}

// ============================================================
// GEMM C[M,1024] = A[M,1024] @ op(B) + bias   (bf16x3)
// TRANSB=0: op(B)=B^T with B[n][k];  TRANSB=1: op(B)=B with B[k][n]
// block 128x64, BK=32, 8 warps (4m x 2n), warp 32x32
// ============================================================
template<bool TRANSB>
__global__ void __launch_bounds__(256) gemm_bf3(
    const float* __restrict__ A, const float* __restrict__ B,
    const float* __restrict__ bias, float* __restrict__ C)
{
    __shared__ __align__(16) uint16_t Ah[128*40], Al[128*40];
    __shared__ __align__(16) uint16_t Bh[64*40],  Bl[64*40];   // trans view: [32][72] = 2304 <= 2560

    int t = threadIdx.x, warp = t>>5, lane = t&31;
    int row0 = blockIdx.y*128, col0 = blockIdx.x*64;
    int wm = (warp>>1)*32, wn = (warp&1)*32;
    int gr = lane>>2, gq = lane&3;
    float acc[2][4][4] = {};

    int arow = t>>1, aseg = (t&1)*16;
    const float* Ap = A + (size_t)(row0+arow)*1024 + aseg;
    int brow = TRANSB ? (t>>3) : (t>>2);
    int bseg = TRANSB ? (t&7)*8 : (t&3)*8;
    const float* Bp = TRANSB ? (B + (size_t)brow*1024 + col0 + bseg)
                             : (B + (size_t)(col0+brow)*1024 + bseg);

    float ar[16], br[8];
    *(float4*)(ar)    = *(const float4*)(Ap);
    *(float4*)(ar+4)  = *(const float4*)(Ap+4);
    *(float4*)(ar+8)  = *(const float4*)(Ap+8);
    *(float4*)(ar+12) = *(const float4*)(Ap+12);
    *(float4*)(br)    = *(const float4*)(Bp);
    *(float4*)(br+4)  = *(const float4*)(Bp+4);

    for (int k0 = 0; k0 < 1024; k0 += 32) {
        uint4 H, L;
        split8(ar,   H, L); *(uint4*)&Ah[arow*40+aseg]   = H; *(uint4*)&Al[arow*40+aseg]   = L;
        split8(ar+8, H, L); *(uint4*)&Ah[arow*40+aseg+8] = H; *(uint4*)&Al[arow*40+aseg+8] = L;
        split8(br,   H, L);
        if (TRANSB) { *(uint4*)&Bh[brow*72+bseg] = H; *(uint4*)&Bl[brow*72+bseg] = L; }
        else        { *(uint4*)&Bh[brow*40+bseg] = H; *(uint4*)&Bl[brow*40+bseg] = L; }
        __syncthreads();
        if (k0 + 32 < 1024) {
            const float* An = Ap + k0 + 32;
            const float* Bn = TRANSB ? (Bp + (size_t)(k0+32)*1024) : (Bp + k0 + 32);
            *(float4*)(ar)    = *(const float4*)(An);
            *(float4*)(ar+4)  = *(const float4*)(An+4);
            *(float4*)(ar+8)  = *(const float4*)(An+8);
            *(float4*)(ar+12) = *(const float4*)(An+12);
            *(float4*)(br)    = *(const float4*)(Bn);
            *(float4*)(br+4)  = *(const float4*)(Bn+4);
        }
        #pragma unroll
        for (int kt = 0; kt < 2; kt++) {
            int kk = kt*16;
            uint32_t bh2[4][2], bl2[4][2];
            #pragma unroll
            for (int p = 0; p < 2; p++) {
                uint32_t r0,r1,r2,r3;
                if (TRANSB) ldsm4t(r0,r1,r2,r3, bt_addr<72>(smaddr(Bh), wn+p*16, kk, lane));
                else        ldsm4 (r0,r1,r2,r3, b_addr<40>(smaddr(Bh), wn+p*16, kk, lane));
                bh2[p*2][0]=r0; bh2[p*2][1]=r1; bh2[p*2+1][0]=r2; bh2[p*2+1][1]=r3;
                if (TRANSB) ldsm4t(r0,r1,r2,r3, bt_addr<72>(smaddr(Bl), wn+p*16, kk, lane));
                else        ldsm4 (r0,r1,r2,r3, b_addr<40>(smaddr(Bl), wn+p*16, kk, lane));
                bl2[p*2][0]=r0; bl2[p*2][1]=r1; bl2[p*2+1][0]=r2; bl2[p*2+1][1]=r3;
            }
            #pragma unroll
            for (int ma = 0; ma < 2; ma++) {
                uint32_t a0,a1,a2,a3, c0,c1,c2,c3;
                ldsm4(a0,a1,a2,a3, a_addr<40>(smaddr(Ah), wm+ma*16, kk, lane));
                ldsm4(c0,c1,c2,c3, a_addr<40>(smaddr(Al), wm+ma*16, kk, lane));
                #pragma unroll
                for (int na = 0; na < 4; na++) {
                    mmabf(acc[ma][na], a0,a1,a2,a3, bh2[na][0],bh2[na][1]);
                    mmabf(acc[ma][na], a0,a1,a2,a3, bl2[na][0],bl2[na][1]);
                    mmabf(acc[ma][na], c0,c1,c2,c3, bh2[na][0],bh2[na][1]);
                }
            }
        }
        __syncthreads();
    }
    #pragma unroll
    for (int ma = 0; ma < 2; ma++)
        #pragma unroll
        for (int na = 0; na < 4; na++) {
            int r = row0 + wm + ma*16 + gr;
            int cn = col0 + wn + na*8 + 2*gq;
            float b0v = bias ? bias[cn] : 0.f, b1v = bias ? bias[cn+1] : 0.f;
            *(float2*)(C + (size_t)r*1024 + cn)     = make_float2(acc[ma][na][0]+b0v, acc[ma][na][1]+b1v);
            *(float2*)(C + (size_t)(r+8)*1024 + cn) = make_float2(acc[ma][na][2]+b0v, acc[ma][na][3]+b1v);
        }
}

// ============================================================
// Logits: qk[bh,i,j] = S2*(q_i.k_j)*gate(j); block 128x128, K=64 (2x BK=32)
// 8 warps (2m x 4n), warp 64x32 (ma=4, na=4)
// ============================================================
__global__ void __launch_bounds__(256) logits_bf3(
    const float* __restrict__ q, const float* __restrict__ k,
    const float* __restrict__ factor, float* __restrict__ qk)
{
    __shared__ __align__(16) uint16_t Ah[128*40], Al[128*40];
    __shared__ __align__(16) uint16_t Bh[128*40], Bl[128*40];
    __shared__ float zf[128];

    int t = threadIdx.x, warp = t>>5, lane = t&31;
    int bhid = blockIdx.z, b = bhid>>4, h = bhid&15;
    int row0 = blockIdx.y*128, col0 = blockIdx.x*128;
    int wm = (warp>>2)*64, wn = (warp&3)*32;
    int gr = lane>>2, gq = lane&3;
    float acc[4][4][4] = {};

    int arow = t>>1, aseg = (t&1)*16;
    const float* Ap = q + (size_t)(b*CTX + row0 + arow)*DIMS + h*HD + aseg;
    const float* Bp = k + (size_t)(b*CTX + col0 + arow)*DIMS + h*HD + aseg;

    if (t < 128) {
        float kf = k[(size_t)(b*CTX + col0 + t)*DIMS + h*HD];
        float f = *factor;
        float zfac = fminf(fmaxf(log1pf(expf(f)), 0.f), 0.001f);
        zf[t] = (kf == 0.f) ? zfac : 1.f;
    }

    #pragma unroll
    for (int k0 = 0; k0 < 64; k0 += 32) {
        float ar[16], br[16];
        *(float4*)(ar)    = *(const float4*)(Ap + k0);
        *(float4*)(ar+4)  = *(const float4*)(Ap + k0 + 4);
        *(float4*)(ar+8)  = *(const float4*)(Ap + k0 + 8);
        *(float4*)(ar+12) = *(const float4*)(Ap + k0 + 12);
        *(float4*)(br)    = *(const float4*)(Bp + k0);
        *(float4*)(br+4)  = *(const float4*)(Bp + k0 + 4);
        *(float4*)(br+8)  = *(const float4*)(Bp + k0 + 8);
        *(float4*)(br+12) = *(const float4*)(Bp + k0 + 12);
        uint4 H, L;
        split8(ar,   H, L); *(uint4*)&Ah[arow*40+aseg]   = H; *(uint4*)&Al[arow*40+aseg]   = L;
        split8(ar+8, H, L); *(uint4*)&Ah[arow*40+aseg+8] = H; *(uint4*)&Al[arow*40+aseg+8] = L;
        split8(br,   H, L); *(uint4*)&Bh[arow*40+aseg]   = H; *(uint4*)&Bl[arow*40+aseg]   = L;
        split8(br+8, H, L); *(uint4*)&Bh[arow*40+aseg+8] = H; *(uint4*)&Bl[arow*40+aseg+8] = L;
        __syncthreads();
        #pragma unroll
        for (int kt = 0; kt < 2; kt++) {
            int kk = kt*16;
            uint32_t bh2[4][2], bl2[4][2];
            #pragma unroll
            for (int p = 0; p < 2; p++) {
                uint32_t r0,r1,r2,r3;
                ldsm4(r0,r1,r2,r3, b_addr<40>(smaddr(Bh), wn+p*16, kk, lane));
                bh2[p*2][0]=r0; bh2[p*2][1]=r1; bh2[p*2+1][0]=r2; bh2[p*2+1][1]=r3;
                ldsm4(r0,r1,r2,r3, b_addr<40>(smaddr(Bl), wn+p*16, kk, lane));
                bl2[p*2][0]=r0; bl2[p*2][1]=r1; bl2[p*2+1][0]=r2; bl2[p*2+1][1]=r3;
            }
            #pragma unroll
            for (int ma = 0; ma < 4; ma++) {
                uint32_t a0,a1,a2,a3, c0,c1,c2,c3;
                ldsm4(a0,a1,a2,a3, a_addr<40>(smaddr(Ah), wm+ma*16, kk, lane));
                ldsm4(c0,c1,c2,c3, a_addr<40>(smaddr(Al), wm+ma*16, kk, lane));
                #pragma unroll
                for (int na = 0; na < 4; na++) {
                    mmabf(acc[ma][na], a0,a1,a2,a3, bh2[na][0],bh2[na][1]);
                    mmabf(acc[ma][na], a0,a1,a2,a3, bl2[na][0],bl2[na][1]);
                    mmabf(acc[ma][na], c0,c1,c2,c3, bh2[na][0],bh2[na][1]);
                }
            }
        }
        __syncthreads();
    }
    const float S2 = 0.125f;
    float* Cb = qk + (size_t)bhid * CTX * CTX;
    #pragma unroll
    for (int ma = 0; ma < 4; ma++)
        #pragma unroll
        for (int na = 0; na < 4; na++) {
            int r  = row0 + wm + ma*16 + gr;
            int cl = wn + na*8 + 2*gq;
            float z0 = zf[cl]*S2, z1 = zf[cl+1]*S2;
            *(float2*)(Cb + (size_t)r*CTX + col0 + cl) =
                make_float2(acc[ma][na][0]*z0, acc[ma][na][1]*z1);
            *(float2*)(Cb + (size_t)(r+8)*CTX + col0 + cl) =
                make_float2(acc[ma][na][2]*z0, acc[ma][na][3]*z1);
        }
}

// ============================================================
// Online-softmax + AV (bf16x3, ldmatrix, V via trans)
// block: 128 q-rows x 64 d; key chunks of 32
// ============================================================
__global__ void __launch_bounds__(256) av_bf3(
    const float* __restrict__ qkbuf, const float* __restrict__ v,
    float* __restrict__ wv)
{
    __shared__ __align__(16) uint16_t Ph[128*40], Pl[128*40];
    __shared__ __align__(16) uint16_t Vh[32*72],  Vl[32*72];
    __shared__ float redmax[128][2], redsum[128][2];
    __shared__ float mrow[128], rsum[128], rscale[128], rinv[128];

    int t = threadIdx.x, warp = t>>5, lane = t&31;
    int bhid = blockIdx.y, b = bhid>>4, h = bhid&15;
    int row0 = blockIdx.x*128;
    int wm = (warp>>1)*32, wn = (warp&1)*32;
    int gr = lane>>2, gq = lane&3;
    const float* L = qkbuf + (size_t)bhid * CTX * CTX;

    int lrow = t>>1, lh2 = t&1, lseg = lh2*16;
    int vrow = t>>3, vseg = (t&7)*8;
    float acc[2][4][4] = {};

    if (t < 128) { mrow[t] = -3.0e38f; rsum[t] = 0.f; redsum[t][0] = 0.f; redsum[t][1] = 0.f; }
    __syncthreads();

    for (int kc = 0; kc < CTX; kc += 32) {
        const float* Lp = L + (size_t)(row0 + lrow)*CTX + kc + lseg;
        float x[16];
        *(float4*)(x)    = *(const float4*)(Lp);
        *(float4*)(x+4)  = *(const float4*)(Lp+4);
        *(float4*)(x+8)  = *(const float4*)(Lp+8);
        *(float4*)(x+12) = *(const float4*)(Lp+12);
        float lm = -3.0e38f;
        #pragma unroll
        for (int j = 0; j < 16; j++) lm = fmaxf(lm, x[j]);
        redmax[lrow][lh2] = lm;

        float vv[8];
        const float* Vp = v + (size_t)(b*CTX + kc + vrow)*DIMS + h*HD + vseg;
        *(float4*)(vv)   = *(const float4*)(Vp);
        *(float4*)(vv+4) = *(const float4*)(Vp+4);
        uint4 H, Lo;
        split8(vv, H, Lo);
        *(uint4*)&Vh[vrow*72+vseg] = H; *(uint4*)&Vl[vrow*72+vseg] = Lo;
        __syncthreads();

        if (t < 128) {
            float cm = fmaxf(redmax[t][0], redmax[t][1]);
            float mo = mrow[t], mn = fmaxf(mo, cm);
            float sc = __expf(mo - mn);
            mrow[t] = mn; rscale[t] = sc;
            rsum[t] = (rsum[t] + redsum[t][0] + redsum[t][1]) * sc;
        }
        __syncthreads();

        float mr = mrow[lrow];
        float e[16], ps = 0.f;
        #pragma unroll
        for (int j = 0; j < 16; j++) { e[j] = __expf(x[j] - mr); ps += e[j]; }
        split8(e,   H, Lo); *(uint4*)&Ph[lrow*40+lseg]   = H; *(uint4*)&Pl[lrow*40+lseg]   = Lo;
        split8(e+8, H, Lo); *(uint4*)&Ph[lrow*40+lseg+8] = H; *(uint4*)&Pl[lrow*40+lseg+8] = Lo;
        redsum[lrow][lh2] = ps;

        #pragma unroll
        for (int ma = 0; ma < 2; ma++) {
            float s0 = rscale[wm + ma*16 + gr];
            float s1 = rscale[wm + ma*16 + gr + 8];
            #pragma unroll
            for (int na = 0; na < 4; na++) {
                acc[ma][na][0] *= s0; acc[ma][na][1] *= s0;
                acc[ma][na][2] *= s1; acc[ma][na][3] *= s1;
            }
        }
        __syncthreads();

        #pragma unroll
        for (int kt = 0; kt < 2; kt++) {
            int kk = kt*16;
            uint32_t bh2[4][2], bl2[4][2];
            #pragma unroll
            for (int p = 0; p < 2; p++) {
                uint32_t r0,r1,r2,r3;
                ldsm4t(r0,r1,r2,r3, bt_addr<72>(smaddr(Vh), wn+p*16, kk, lane));
                bh2[p*2][0]=r0; bh2[p*2][1]=r1; bh2[p*2+1][0]=r2; bh2[p*2+1][1]=r3;
                ldsm4t(r0,r1,r2,r3, bt_addr<72>(smaddr(Vl), wn+p*16, kk, lane));
                bl2[p*2][0]=r0; bl2[p*2][1]=r1; bl2[p*2+1][0]=r2; bl2[p*2+1][1]=r3;
            }
            #pragma unroll
            for (int ma = 0; ma < 2; ma++) {
                uint32_t a0,a1,a2,a3, c0,c1,c2,c3;
                ldsm4(a0,a1,a2,a3, a_addr<40>(smaddr(Ph), wm+ma*16, kk, lane));
                ldsm4(c0,c1,c2,c3, a_addr<40>(smaddr(Pl), wm+ma*16, kk, lane));
                #pragma unroll
                for (int na = 0; na < 4; na++) {
                    mmabf(acc[ma][na], a0,a1,a2,a3, bh2[na][0],bh2[na][1]);
                    mmabf(acc[ma][na], a0,a1,a2,a3, bl2[na][0],bl2[na][1]);
                    mmabf(acc[ma][na], c0,c1,c2,c3, bh2[na][0],bh2[na][1]);
                }
            }
        }
        __syncthreads();
    }

    if (t < 128) rinv[t] = 1.f / (rsum[t] + redsum[t][0] + redsum[t][1]);
    __syncthreads();

    #pragma unroll
    for (int ma = 0; ma < 2; ma++)
        #pragma unroll
        for (int na = 0; na < 4; na++) {
            int rl = wm + ma*16 + gr;
            int cn = h*HD + wn + na*8 + 2*gq;
            float i0 = rinv[rl], i1 = rinv[rl+8];
            *(float2*)(wv + (size_t)(b*CTX + row0 + rl)*DIMS + cn) =
                make_float2(acc[ma][na][0]*i0, acc[ma][na][1]*i0);
            *(float2*)(wv + (size_t)(b*CTX + row0 + rl + 8)*DIMS + cn) =
                make_float2(acc[ma][na][2]*i1, acc[ma][na][3]*i1);
        }
}

// ============================================================
// bias2[n] = sum_k bout[k]*Wout[n][k] + bout[n]
// ============================================================
__global__ void __launch_bounds__(256) bias2_k(
    const float* __restrict__ W, const float* __restrict__ b, float* __restrict__ out)
{
    int n = blockIdx.x*8 + (threadIdx.x>>5);
    int lane = threadIdx.x & 31;
    float s = 0.f;
    for (int k = lane; k < 1024; k += 32) s += b[k] * W[(size_t)n*1024 + k];
    #pragma unroll
    for (int o = 16; o; o >>= 1) s += __shfl_xor_sync(0xffffffffu, s, o);
    if (lane == 0) out[n] = s + b[n];
}

// ============================================================
extern "C" void kernel_launch(void* const* d_in, const int* in_sizes, int n_in,
                              void* d_out, int out_size)
{
    const float* x    = (const float*)d_in[0];
    const float* Wq   = (const float*)d_in[1];
    const float* bq   = (const float*)d_in[2];
    const float* Wk   = (const float*)d_in[3];
    const float* Wv   = (const float*)d_in[4];
    const float* bv   = (const float*)d_in[5];
    const float* Wout = (const float*)d_in[6];
    const float* bout = (const float*)d_in[7];
    const float* factor = (const float*)d_in[8];

    float *qp, *kp, *vp, *wvp, *w2p, *b2p, *qkfb;
    cudaGetSymbolAddress((void**)&qp,  g_q);
    cudaGetSymbolAddress((void**)&kp,  g_k);
    cudaGetSymbolAddress((void**)&vp,  g_v);
    cudaGetSymbolAddress((void**)&wvp, g_wv);
    cudaGetSymbolAddress((void**)&w2p, g_w2);
    cudaGetSymbolAddress((void**)&b2p, g_b2);
    cudaGetSymbolAddress((void**)&qkfb, g_qk_fallback);

    float* out = (float*)d_out;
    float* qkdst = ((size_t)out_size >= (size_t)OUT_ELEMS + QK_ELEMS)
                 ? (out + OUT_ELEMS) : qkfb;

    // W2 = Wout @ Wout  (trans-B), bias2 = bout@Wout^T + bout
    gemm_bf3<true><<<dim3(16, 8), 256>>>(Wout, Wout, nullptr, w2p);
    bias2_k<<<128, 256>>>(Wout, bout, b2p);

    dim3 gp(16, 32);
    gemm_bf3<false><<<gp, 256>>>(x, Wq, bq,      qp);
    gemm_bf3<false><<<gp, 256>>>(x, Wk, nullptr, kp);
    gemm_bf3<false><<<gp, 256>>>(x, Wv, bv,      vp);

    logits_bf3<<<dim3(16, 16, 32), 256>>>(qp, kp, factor, qkdst);
    av_bf3<<<dim3(16, 32), 256>>>(qkdst, vp, wvp);

    // out = wv @ W2^T + bias2   (single fused out-projection)
    gemm_bf3<false><<<gp, 256>>>(wvp, w2p, b2p, out);
}

// round 8
// speedup vs baseline: 2.3873x; 1.1857x over previous
#include <cuda_runtime.h>
#include <cuda_bf16.h>
#include <math.h>
#include <stdint.h>

#define DIMS 1024
#define HEAD 16
#define HD   64
#define CTX  2048
#define BATCH 2
#define MROWS (BATCH*CTX)
#define OUT_ELEMS (MROWS*DIMS)
#define QK_ELEMS  ((size_t)BATCH*HEAD*CTX*CTX)

typedef unsigned short u16;
typedef unsigned int   u32;

// ---- scratch (device globals, alloc-free) ----
__device__ u16 g_xh [MROWS*DIMS], g_xl [MROWS*DIMS];
__device__ u16 g_Wqh[DIMS*DIMS],  g_Wql[DIMS*DIMS];
__device__ u16 g_Wkh[DIMS*DIMS],  g_Wkl[DIMS*DIMS];
__device__ u16 g_Wvh[DIMS*DIMS],  g_Wvl[DIMS*DIMS];
__device__ u16 g_Woh[DIMS*DIMS],  g_Wol[DIMS*DIMS];     // Wout split
__device__ u16 g_Wth[DIMS*DIMS],  g_Wtl[DIMS*DIMS];     // Wout^T split
__device__ u16 g_W2h[DIMS*DIMS],  g_W2l[DIMS*DIMS];     // (Wout@Wout) split
__device__ float g_b2[DIMS];
__device__ u16 g_qh [MROWS*DIMS], g_ql [MROWS*DIMS];
__device__ u16 g_kh [MROWS*DIMS], g_kl [MROWS*DIMS];
__device__ u16 g_vh [MROWS*DIMS], g_vl [MROWS*DIMS];
__device__ u16 g_avh[MROWS*DIMS], g_avl[MROWS*DIMS];
__device__ float g_kc0[HEAD*MROWS];
__device__ float g_qk_fallback[QK_ELEMS];

// ---- helpers ----
__device__ __forceinline__ u32 smaddr(const void* p){
    return (u32)__cvta_generic_to_shared(p);
}
__device__ __forceinline__ void ldsm4(u32&r0,u32&r1,u32&r2,u32&r3,u32 a){
    asm volatile("ldmatrix.sync.aligned.m8n8.x4.shared.b16 {%0,%1,%2,%3},[%4];"
        :"=r"(r0),"=r"(r1),"=r"(r2),"=r"(r3):"r"(a));
}
__device__ __forceinline__ void ldsm4t(u32&r0,u32&r1,u32&r2,u32&r3,u32 a){
    asm volatile("ldmatrix.sync.aligned.m8n8.x4.trans.shared.b16 {%0,%1,%2,%3},[%4];"
        :"=r"(r0),"=r"(r1),"=r"(r2),"=r"(r3):"r"(a));
}
__device__ __forceinline__ void mmabf(float c[4],
    u32 a0,u32 a1,u32 a2,u32 a3,u32 b0,u32 b1){
    asm volatile("mma.sync.aligned.m16n8k16.row.col.f32.bf16.bf16.f32 "
        "{%0,%1,%2,%3},{%4,%5,%6,%7},{%8,%9},{%0,%1,%2,%3};"
        :"+f"(c[0]),"+f"(c[1]),"+f"(c[2]),"+f"(c[3])
        :"r"(a0),"r"(a1),"r"(a2),"r"(a3),"r"(b0),"r"(b1));
}
__device__ __forceinline__ u32 packbf(float x, float y){
    __nv_bfloat162 t = __floats2bfloat162_rn(x,y);
    return *reinterpret_cast<u32*>(&t);
}
__device__ __forceinline__ u32 split_pair(float v0, float v1, u32& lo){
    __nv_bfloat16 h0=__float2bfloat16(v0), h1=__float2bfloat16(v1);
    float l0 = v0-__bfloat162float(h0), l1 = v1-__bfloat162float(h1);
    lo = packbf(l0,l1);
    __nv_bfloat162 hh; hh.x=h0; hh.y=h1;
    return *reinterpret_cast<u32*>(&hh);
}
__device__ __forceinline__ void cpa16(u32 dst, const void* src){
    asm volatile("cp.async.cg.shared.global [%0],[%1],16;"::"r"(dst),"l"(src));
}
#define CPA_COMMIT() asm volatile("cp.async.commit_group;"::)
#define CPA_WAIT0()  asm volatile("cp.async.wait_group 0;"::)

template<int S>
__device__ __forceinline__ u32 a_addr(u32 base, int r0, int k0, int lane){
    int r = r0 + (lane&7) + ((lane>>3)&1)*8;
    int k = k0 + ((lane>>4)&1)*8;
    return base + (u32)(r*S + k)*2;
}
template<int S>
__device__ __forceinline__ u32 b_addr(u32 base, int n0, int k0, int lane){
    int n = n0 + (lane&7) + ((lane>>4)&1)*8;
    int k = k0 + ((lane>>3)&1)*8;
    return base + (u32)(n*S + k)*2;
}
template<int S>
__device__ __forceinline__ u32 bt_addr(u32 base, int n0, int k0, int lane){
    int k = k0 + (lane&7) + ((lane>>3)&1)*8;
    int n = n0 + ((lane>>4)&1)*8;
    return base + (u32)(k*S + n)*2;
}

// ============================================================
// converts
// ============================================================
__global__ void __launch_bounds__(256) conv_split(
    const float* __restrict__ s, u16* __restrict__ h, u16* __restrict__ l, int n)
{
    int i = (blockIdx.x*256 + threadIdx.x)*8;
    if (i >= n) return;
    float4 x0 = *(const float4*)(s+i), x1 = *(const float4*)(s+i+4);
    float xs[8] = {x0.x,x0.y,x0.z,x0.w,x1.x,x1.y,x1.z,x1.w};
    u32 H[4], L[4];
    #pragma unroll
    for (int j=0;j<4;j++) H[j] = split_pair(xs[2*j], xs[2*j+1], L[j]);
    *(uint4*)(h+i) = make_uint4(H[0],H[1],H[2],H[3]);
    *(uint4*)(l+i) = make_uint4(L[0],L[1],L[2],L[3]);
}

// transpose + split: out[n][k] = s[k][n]
__global__ void __launch_bounds__(256) conv_split_t(
    const float* __restrict__ s, u16* __restrict__ h, u16* __restrict__ l)
{
    __shared__ float tile[32][33];
    int bx = blockIdx.x*32, by = blockIdx.y*32;
    int tx = threadIdx.x&31, ty = threadIdx.x>>5;
    for (int i = ty; i < 32; i += 8)
        tile[i][tx] = s[(size_t)(by+i)*DIMS + bx+tx];
    __syncthreads();
    for (int i = ty; i < 32; i += 8) {
        float v = tile[tx][i];
        __nv_bfloat16 hb = __float2bfloat16(v);
        h[(size_t)(bx+i)*DIMS + by+tx] = *(u16*)&hb;
        float lv = v - __bfloat162float(hb);
        __nv_bfloat16 lb = __float2bfloat16(lv);
        l[(size_t)(bx+i)*DIMS + by+tx] = *(u16*)&lb;
    }
}

// bias2[n] = sum_k bout[k]*Wout[n][k] + bout[n]
__global__ void __launch_bounds__(256) bias2_k(
    const float* __restrict__ W, const float* __restrict__ b, float* __restrict__ out)
{
    int n = blockIdx.x*8 + (threadIdx.x>>5);
    int lane = threadIdx.x & 31;
    float s = 0.f;
    for (int k = lane; k < 1024; k += 32) s += b[k] * W[(size_t)n*1024 + k];
    #pragma unroll
    for (int o = 16; o; o >>= 1) s += __shfl_xor_sync(0xffffffffu, s, o);
    if (lane == 0) out[n] = s + b[n];
}

// ============================================================
// bf16x3 GEMM, preconverted inputs: C[M,1024] = A@B^T (+bias)
// MODE 0: bf16 h/l out; 1: + kcol0 spill; 2: fp32 out
// tile 128x128, BK=32, 8 warps (2m x 4n), cp.async double buffer
// smem: 2 bufs x 4 mats x 5120 u16 = 81920 B (dynamic)
// ============================================================
template<int MODE>
__global__ void __launch_bounds__(256) gemm_pp(
    const u16* __restrict__ Agh, const u16* __restrict__ Agl,
    const u16* __restrict__ Bgh, const u16* __restrict__ Bgl,
    const float* __restrict__ bias,
    u16* __restrict__ Ch, u16* __restrict__ Cl,
    float* __restrict__ Cf, float* __restrict__ kc0)
{
    extern __shared__ u16 smp[];
    int t=threadIdx.x, warp=t>>5, lane=t&31;
    int row0=blockIdx.y*128, col0=blockIdx.x*128;
    int wm=(warp>>2)*64, wn=(warp&3)*32;
    int gr=lane>>2, gq=lane&3;
    float acc[4][4][4]={};

    int lrow=t>>1, lseg=(t&1)*16;
    const u16* Ash = Agh + (size_t)(row0+lrow)*DIMS + lseg;
    const u16* Asl = Agl + (size_t)(row0+lrow)*DIMS + lseg;
    const u16* Bsh = Bgh + (size_t)(col0+lrow)*DIMS + lseg;
    const u16* Bsl = Bgl + (size_t)(col0+lrow)*DIMS + lseg;
    u32 dsm = smaddr(smp) + (u32)(lrow*40+lseg)*2;

    auto issue = [&](int it, int buf){
        u32 d = dsm + buf*40960;
        cpa16(d,          Ash+it*32); cpa16(d+16,          Ash+it*32+8);
        cpa16(d+10240,    Asl+it*32); cpa16(d+10240+16,    Asl+it*32+8);
        cpa16(d+20480,    Bsh+it*32); cpa16(d+20480+16,    Bsh+it*32+8);
        cpa16(d+30720,    Bsl+it*32); cpa16(d+30720+16,    Bsl+it*32+8);
    };
    issue(0,0); CPA_COMMIT();

    for (int it=0; it<32; it++){
        int buf=it&1;
        CPA_WAIT0();
        __syncthreads();
        if (it+1<32){ issue(it+1,buf^1); CPA_COMMIT(); }
        u32 Ah = smaddr(smp) + buf*40960;
        u32 Al = Ah+10240, Bh = Ah+20480, Bl = Ah+30720;
        #pragma unroll
        for (int ksi=0;ksi<2;ksi++){
            int kk=ksi*16;
            u32 ah[4][4], al[4][4], bh2[4][2], bl2[4][2];
            #pragma unroll
            for (int m2=0;m2<4;m2++){
                ldsm4(ah[m2][0],ah[m2][1],ah[m2][2],ah[m2][3], a_addr<40>(Ah, wm+m2*16, kk, lane));
                ldsm4(al[m2][0],al[m2][1],al[m2][2],al[m2][3], a_addr<40>(Al, wm+m2*16, kk, lane));
            }
            #pragma unroll
            for (int pp=0;pp<2;pp++){
                u32 r0,r1,r2,r3;
                ldsm4(r0,r1,r2,r3, b_addr<40>(Bh, wn+pp*16, kk, lane));
                bh2[2*pp][0]=r0; bh2[2*pp][1]=r1; bh2[2*pp+1][0]=r2; bh2[2*pp+1][1]=r3;
                ldsm4(r0,r1,r2,r3, b_addr<40>(Bl, wn+pp*16, kk, lane));
                bl2[2*pp][0]=r0; bl2[2*pp][1]=r1; bl2[2*pp+1][0]=r2; bl2[2*pp+1][1]=r3;
            }
            #pragma unroll
            for (int m2=0;m2<4;m2++)
                #pragma unroll
                for (int na=0;na<4;na++){
                    mmabf(acc[m2][na], ah[m2][0],ah[m2][1],ah[m2][2],ah[m2][3], bh2[na][0],bh2[na][1]);
                    mmabf(acc[m2][na], ah[m2][0],ah[m2][1],ah[m2][2],ah[m2][3], bl2[na][0],bl2[na][1]);
                    mmabf(acc[m2][na], al[m2][0],al[m2][1],al[m2][2],al[m2][3], bh2[na][0],bh2[na][1]);
                }
        }
    }
    #pragma unroll
    for (int m2=0;m2<4;m2++)
        #pragma unroll
        for (int na=0;na<4;na++){
            int r  = row0+wm+m2*16+gr;
            int cn = col0+wn+na*8+2*gq;
            float b0v = bias? bias[cn]:0.f, b1v = bias? bias[cn+1]:0.f;
            float v0=acc[m2][na][0]+b0v, v1=acc[m2][na][1]+b1v;
            float v2=acc[m2][na][2]+b0v, v3=acc[m2][na][3]+b1v;
            if (MODE==2){
                *(float2*)(Cf+(size_t)r*DIMS+cn)     = make_float2(v0,v1);
                *(float2*)(Cf+(size_t)(r+8)*DIMS+cn) = make_float2(v2,v3);
            } else {
                u32 lo,hi;
                hi=split_pair(v0,v1,lo);
                *(u32*)(Ch+(size_t)r*DIMS+cn)=hi;  *(u32*)(Cl+(size_t)r*DIMS+cn)=lo;
                hi=split_pair(v2,v3,lo);
                *(u32*)(Ch+(size_t)(r+8)*DIMS+cn)=hi; *(u32*)(Cl+(size_t)(r+8)*DIMS+cn)=lo;
                if (MODE==1 && gq==0 && (((wn+na*8)&63)==0)){
                    int hh = cn>>6;
                    kc0[hh*MROWS + r]   = v0;
                    kc0[hh*MROWS + r+8] = v2;
                }
            }
        }
}

// ============================================================
// Fused logits + qk-spill + online softmax + AV
// grid (16, 32): 128 q-rows per CTA, one (b,h). 8 warps x 16 rows.
// key chunks of 64, cp.async double-buffered K/V.
// dyn smem: Q(2x9216) P(2x9216) KV(2x18432) u16 + 64 floats = 147712 B
// ============================================================
__global__ void __launch_bounds__(256) attn_fused(
    const u16* __restrict__ qh_g, const u16* __restrict__ ql_g,
    const u16* __restrict__ kh_g, const u16* __restrict__ kl_g,
    const u16* __restrict__ vh_g, const u16* __restrict__ vl_g,
    const float* __restrict__ kc0, const float* __restrict__ factor,
    float* __restrict__ qk, u16* __restrict__ avh_g, u16* __restrict__ avl_g)
{
    extern __shared__ u16 sma[];
    u16 *Qh_p = sma, *Ql_p = sma+9216, *Ph_p = sma+18432, *Pl_p = sma+27648;
    u16 *KV_p = sma+36864;
    float* gz = (float*)(sma + 73728);

    int t=threadIdx.x, warp=t>>5, lane=t&31;
    int qb=blockIdx.x, bh=blockIdx.y, b=bh>>4, h=bh&15;
    int row0=qb*128, wm=warp*16;
    int gr=lane>>2, gq=lane&3;

    float zfac; { float f=*factor; zfac=fminf(fmaxf(log1pf(expf(f)),0.f),0.001f); }

    // stage Q
    {
        int row=t>>1, half=(t&1)*32;
        const u16* sh = qh_g + (size_t)(b*CTX+row0+row)*DIMS + h*HD + half;
        const u16* sl = ql_g + (size_t)(b*CTX+row0+row)*DIMS + h*HD + half;
        u32 dh = smaddr(Qh_p) + (u32)(row*72+half)*2;
        u32 dl = smaddr(Ql_p) + (u32)(row*72+half)*2;
        #pragma unroll
        for (int c=0;c<32;c+=8){ cpa16(dh+c*2, sh+c); cpa16(dl+c*2, sl+c); }
    }
    int krow=t>>2, kseg=(t&3)*16;
    auto issue_kv=[&](int it, int buf){
        size_t g = (size_t)(b*CTX + it*64 + krow)*DIMS + h*HD + kseg;
        u32 d = smaddr(KV_p) + buf*36864 + (u32)(krow*72+kseg)*2;
        cpa16(d,         kh_g+g); cpa16(d+16,         kh_g+g+8);
        cpa16(d+9216,    kl_g+g); cpa16(d+9216+16,    kl_g+g+8);
        cpa16(d+18432,   vh_g+g); cpa16(d+18432+16,   vh_g+g+8);
        cpa16(d+27648,   vl_g+g); cpa16(d+27648+16,   vl_g+g+8);
    };
    issue_kv(0,0); CPA_COMMIT();

    float m0=-3.0e38f, m1=-3.0e38f, s0=0.f, s1=0.f;
    float acc_o[8][4]={};
    u32 qfh[4][4], qfl[4][4];
    float* Lb = qk + (size_t)bh*CTX*CTX;
    int rg0 = row0+wm+gr;

    for (int it=0; it<32; it++){
        int buf=it&1;
        u16 *Kh_p = KV_p + buf*18432, *Kl_p = Kh_p+4608;
        u16 *Vh_p = Kh_p + 9216,      *Vl_p = Kh_p+13824;
        CPA_WAIT0();
        __syncthreads();
        if (it==0){
            #pragma unroll
            for (int ks=0;ks<4;ks++){
                ldsm4(qfh[ks][0],qfh[ks][1],qfh[ks][2],qfh[ks][3], a_addr<72>(smaddr(Qh_p), wm, ks*16, lane));
                ldsm4(qfl[ks][0],qfl[ks][1],qfl[ks][2],qfl[ks][3], a_addr<72>(smaddr(Ql_p), wm, ks*16, lane));
            }
        }
        if (it+1<32){ issue_kv(it+1,buf^1); CPA_COMMIT(); }
        if (t<64){
            float kv0 = kc0[h*MROWS + b*CTX + it*64 + t];
            gz[t] = (kv0==0.f)? zfac : 1.f;
        }
        // S = Q @ K^T
        float sacc[8][4]={};
        #pragma unroll
        for (int ks=0;ks<4;ks++){
            u32 bh2[8][2], bl2[8][2];
            #pragma unroll
            for (int pp=0;pp<4;pp++){
                u32 r0,r1,r2,r3;
                ldsm4(r0,r1,r2,r3, b_addr<72>(smaddr(Kh_p), pp*16, ks*16, lane));
                bh2[2*pp][0]=r0; bh2[2*pp][1]=r1; bh2[2*pp+1][0]=r2; bh2[2*pp+1][1]=r3;
                ldsm4(r0,r1,r2,r3, b_addr<72>(smaddr(Kl_p), pp*16, ks*16, lane));
                bl2[2*pp][0]=r0; bl2[2*pp][1]=r1; bl2[2*pp+1][0]=r2; bl2[2*pp+1][1]=r3;
            }
            #pragma unroll
            for (int na=0;na<8;na++){
                mmabf(sacc[na], qfh[ks][0],qfh[ks][1],qfh[ks][2],qfh[ks][3], bh2[na][0],bh2[na][1]);
                mmabf(sacc[na], qfh[ks][0],qfh[ks][1],qfh[ks][2],qfh[ks][3], bl2[na][0],bl2[na][1]);
                mmabf(sacc[na], qfl[ks][0],qfl[ks][1],qfl[ks][2],qfl[ks][3], bh2[na][0],bh2[na][1]);
            }
        }
        __syncthreads();   // gz visible
        // scale+gate, spill qk, row max
        float lm0=-3.0e38f, lm1=-3.0e38f;
        int kb = it*64;
        #pragma unroll
        for (int na=0;na<8;na++){
            int col=na*8+2*gq;
            float z0=gz[col]*0.125f, z1=gz[col+1]*0.125f;
            sacc[na][0]*=z0; sacc[na][1]*=z1; sacc[na][2]*=z0; sacc[na][3]*=z1;
            *(float2*)(Lb+(size_t)rg0*CTX+kb+col)     = make_float2(sacc[na][0],sacc[na][1]);
            *(float2*)(Lb+(size_t)(rg0+8)*CTX+kb+col) = make_float2(sacc[na][2],sacc[na][3]);
            lm0=fmaxf(lm0,fmaxf(sacc[na][0],sacc[na][1]));
            lm1=fmaxf(lm1,fmaxf(sacc[na][2],sacc[na][3]));
        }
        lm0=fmaxf(lm0,__shfl_xor_sync(0xffffffffu,lm0,1));
        lm0=fmaxf(lm0,__shfl_xor_sync(0xffffffffu,lm0,2));
        lm1=fmaxf(lm1,__shfl_xor_sync(0xffffffffu,lm1,1));
        lm1=fmaxf(lm1,__shfl_xor_sync(0xffffffffu,lm1,2));
        float mn0=fmaxf(m0,lm0), mn1=fmaxf(m1,lm1);
        float r0s=__expf(m0-mn0), r1s=__expf(m1-mn1);
        m0=mn0; m1=mn1; s0*=r0s; s1*=r1s;
        float ps0=0.f, ps1=0.f;
        #pragma unroll
        for (int na=0;na<8;na++){
            float p0=__expf(sacc[na][0]-mn0), p1=__expf(sacc[na][1]-mn0);
            float p2=__expf(sacc[na][2]-mn1), p3=__expf(sacc[na][3]-mn1);
            ps0+=p0+p1; ps1+=p2+p3;
            int col=na*8+2*gq;
            u32 lo,hi;
            hi=split_pair(p0,p1,lo);
            *(u32*)(Ph_p + (wm+gr)*72 + col)=hi; *(u32*)(Pl_p + (wm+gr)*72 + col)=lo;
            hi=split_pair(p2,p3,lo);
            *(u32*)(Ph_p + (wm+gr+8)*72 + col)=hi; *(u32*)(Pl_p + (wm+gr+8)*72 + col)=lo;
            acc_o[na][0]*=r0s; acc_o[na][1]*=r0s; acc_o[na][2]*=r1s; acc_o[na][3]*=r1s;
        }
        ps0+=__shfl_xor_sync(0xffffffffu,ps0,1); ps0+=__shfl_xor_sync(0xffffffffu,ps0,2);
        ps1+=__shfl_xor_sync(0xffffffffu,ps1,1); ps1+=__shfl_xor_sync(0xffffffffu,ps1,2);
        s0+=ps0; s1+=ps1;
        __syncthreads();   // P visible
        // acc_o += P @ V
        #pragma unroll
        for (int ks=0;ks<4;ks++){
            u32 a0,a1,a2,a3,c0,c1,c2,c3;
            ldsm4(a0,a1,a2,a3, a_addr<72>(smaddr(Ph_p), wm, ks*16, lane));
            ldsm4(c0,c1,c2,c3, a_addr<72>(smaddr(Pl_p), wm, ks*16, lane));
            u32 bh2[8][2], bl2[8][2];
            #pragma unroll
            for (int pp=0;pp<4;pp++){
                u32 r0,r1,r2,r3;
                ldsm4t(r0,r1,r2,r3, bt_addr<72>(smaddr(Vh_p), pp*16, ks*16, lane));
                bh2[2*pp][0]=r0; bh2[2*pp][1]=r1; bh2[2*pp+1][0]=r2; bh2[2*pp+1][1]=r3;
                ldsm4t(r0,r1,r2,r3, bt_addr<72>(smaddr(Vl_p), pp*16, ks*16, lane));
                bl2[2*pp][0]=r0; bl2[2*pp][1]=r1; bl2[2*pp+1][0]=r2; bl2[2*pp+1][1]=r3;
            }
            #pragma unroll
            for (int na=0;na<8;na++){
                mmabf(acc_o[na], a0,a1,a2,a3, bh2[na][0],bh2[na][1]);
                mmabf(acc_o[na], a0,a1,a2,a3, bl2[na][0],bl2[na][1]);
                mmabf(acc_o[na], c0,c1,c2,c3, bh2[na][0],bh2[na][1]);
            }
        }
    }
    // epilogue: normalize, write wv as bf16 h/l
    float i0=1.f/s0, i1=1.f/s1;
    #pragma unroll
    for (int na=0;na<8;na++){
        int col=na*8+2*gq;
        size_t o0=(size_t)(b*CTX+rg0)*DIMS + h*HD + col;
        size_t o1=(size_t)(b*CTX+rg0+8)*DIMS + h*HD + col;
        u32 lo,hi;
        hi=split_pair(acc_o[na][0]*i0, acc_o[na][1]*i0, lo);
        *(u32*)(avh_g+o0)=hi; *(u32*)(avl_g+o0)=lo;
        hi=split_pair(acc_o[na][2]*i1, acc_o[na][3]*i1, lo);
        *(u32*)(avh_g+o1)=hi; *(u32*)(avl_g+o1)=lo;
    }
}

// ============================================================
extern "C" void kernel_launch(void* const* d_in, const int* in_sizes, int n_in,
                              void* d_out, int out_size)
{
    const float* x    = (const float*)d_in[0];
    const float* Wq   = (const float*)d_in[1];
    const float* bq   = (const float*)d_in[2];
    const float* Wk   = (const float*)d_in[3];
    const float* Wv   = (const float*)d_in[4];
    const float* bv   = (const float*)d_in[5];
    const float* Wout = (const float*)d_in[6];
    const float* bout = (const float*)d_in[7];
    const float* factor = (const float*)d_in[8];

    u16 *xh,*xl,*wqh,*wql,*wkh,*wkl,*wvh,*wvl,*woh,*wol,*wth,*wtl,*w2h,*w2l;
    u16 *qh,*ql,*kh,*kl,*vh,*vl,*avh,*avl;
    float *b2,*kc0,*qkfb;
    cudaGetSymbolAddress((void**)&xh,  g_xh);  cudaGetSymbolAddress((void**)&xl,  g_xl);
    cudaGetSymbolAddress((void**)&wqh, g_Wqh); cudaGetSymbolAddress((void**)&wql, g_Wql);
    cudaGetSymbolAddress((void**)&wkh, g_Wkh); cudaGetSymbolAddress((void**)&wkl, g_Wkl);
    cudaGetSymbolAddress((void**)&wvh, g_Wvh); cudaGetSymbolAddress((void**)&wvl, g_Wvl);
    cudaGetSymbolAddress((void**)&woh, g_Woh); cudaGetSymbolAddress((void**)&wol, g_Wol);
    cudaGetSymbolAddress((void**)&wth, g_Wth); cudaGetSymbolAddress((void**)&wtl, g_Wtl);
    cudaGetSymbolAddress((void**)&w2h, g_W2h); cudaGetSymbolAddress((void**)&w2l, g_W2l);
    cudaGetSymbolAddress((void**)&qh,  g_qh);  cudaGetSymbolAddress((void**)&ql,  g_ql);
    cudaGetSymbolAddress((void**)&kh,  g_kh);  cudaGetSymbolAddress((void**)&kl,  g_kl);
    cudaGetSymbolAddress((void**)&vh,  g_vh);  cudaGetSymbolAddress((void**)&vl,  g_vl);
    cudaGetSymbolAddress((void**)&avh, g_avh); cudaGetSymbolAddress((void**)&avl, g_avl);
    cudaGetSymbolAddress((void**)&b2,  g_b2);
    cudaGetSymbolAddress((void**)&kc0, g_kc0);
    cudaGetSymbolAddress((void**)&qkfb, g_qk_fallback);

    float* out = (float*)d_out;
    float* qkdst = ((size_t)out_size >= (size_t)OUT_ELEMS + QK_ELEMS)
                 ? (out + OUT_ELEMS) : qkfb;

    const int GSM = 81920, ASM = 147712;
    cudaFuncSetAttribute(gemm_pp<0>, cudaFuncAttributeMaxDynamicSharedMemorySize, GSM);
    cudaFuncSetAttribute(gemm_pp<1>, cudaFuncAttributeMaxDynamicSharedMemorySize, GSM);
    cudaFuncSetAttribute(gemm_pp<2>, cudaFuncAttributeMaxDynamicSharedMemorySize, GSM);
    cudaFuncSetAttribute(attn_fused, cudaFuncAttributeMaxDynamicSharedMemorySize, ASM);

    // converts
    conv_split<<<2048,256>>>(x,    xh,  xl,  MROWS*DIMS);
    conv_split<<<512, 256>>>(Wq,   wqh, wql, DIMS*DIMS);
    conv_split<<<512, 256>>>(Wk,   wkh, wkl, DIMS*DIMS);
    conv_split<<<512, 256>>>(Wv,   wvh, wvl, DIMS*DIMS);
    conv_split<<<512, 256>>>(Wout, woh, wol, DIMS*DIMS);
    conv_split_t<<<dim3(32,32),256>>>(Wout, wth, wtl);
    bias2_k<<<128,256>>>(Wout, bout, b2);

    // W2 = Wout @ Wout  (A=Wout, B=Wout^T as [n][k])
    gemm_pp<0><<<dim3(8,8),  256, GSM>>>(woh, wol, wth, wtl, nullptr, w2h, w2l, nullptr, nullptr);

    // projections
    gemm_pp<0><<<dim3(8,32), 256, GSM>>>(xh, xl, wqh, wql, bq,      qh, ql, nullptr, nullptr);
    gemm_pp<1><<<dim3(8,32), 256, GSM>>>(xh, xl, wkh, wkl, nullptr, kh, kl, nullptr, kc0);
    gemm_pp<0><<<dim3(8,32), 256, GSM>>>(xh, xl, wvh, wvl, bv,      vh, vl, nullptr, nullptr);

    // fused attention (spills qk)
    attn_fused<<<dim3(16,32), 256, ASM>>>(qh,ql,kh,kl,vh,vl, kc0, factor, qkdst, avh, avl);

    // out = wv @ W2^T + b2
    gemm_pp<2><<<dim3(8,32), 256, GSM>>>(avh, avl, w2h, w2l, b2, nullptr, nullptr, out, nullptr);
}

// round 9
// speedup vs baseline: 2.9667x; 1.2427x over previous
#include <cuda_runtime.h>
#include <cuda_bf16.h>
#include <math.h>
#include <stdint.h>

#define DIMS 1024
#define HEAD 16
#define HD   64
#define CTX  2048
#define BATCH 2
#define MROWS (BATCH*CTX)
#define OUT_ELEMS (MROWS*DIMS)
#define QK_ELEMS  ((size_t)BATCH*HEAD*CTX*CTX)

typedef unsigned short u16;
typedef unsigned int   u32;

// ---- scratch ----
__device__ u16 g_xh [MROWS*DIMS], g_xl [MROWS*DIMS];
__device__ u16 g_Wqh[DIMS*DIMS],  g_Wql[DIMS*DIMS];
__device__ u16 g_Wkh[DIMS*DIMS],  g_Wkl[DIMS*DIMS];
__device__ u16 g_Wvh[DIMS*DIMS],  g_Wvl[DIMS*DIMS];
__device__ u16 g_Woh[DIMS*DIMS],  g_Wol[DIMS*DIMS];
__device__ u16 g_Wth[DIMS*DIMS],  g_Wtl[DIMS*DIMS];
__device__ u16 g_W2h[DIMS*DIMS],  g_W2l[DIMS*DIMS];
__device__ float g_b2[DIMS];
__device__ u16 g_qh [MROWS*DIMS], g_ql [MROWS*DIMS];
__device__ u16 g_kh [MROWS*DIMS], g_kl [MROWS*DIMS];
__device__ u16 g_vh [MROWS*DIMS], g_vl [MROWS*DIMS];
__device__ u16 g_avh[MROWS*DIMS], g_avl[MROWS*DIMS];
__device__ float g_kc0[HEAD*MROWS];
__device__ float g_qk_fallback[QK_ELEMS];

// ---- helpers ----
__device__ __forceinline__ u32 smaddr(const void* p){ return (u32)__cvta_generic_to_shared(p); }
__device__ __forceinline__ void ldsm4(u32&r0,u32&r1,u32&r2,u32&r3,u32 a){
    asm volatile("ldmatrix.sync.aligned.m8n8.x4.shared.b16 {%0,%1,%2,%3},[%4];"
        :"=r"(r0),"=r"(r1),"=r"(r2),"=r"(r3):"r"(a));
}
__device__ __forceinline__ void ldsm4t(u32&r0,u32&r1,u32&r2,u32&r3,u32 a){
    asm volatile("ldmatrix.sync.aligned.m8n8.x4.trans.shared.b16 {%0,%1,%2,%3},[%4];"
        :"=r"(r0),"=r"(r1),"=r"(r2),"=r"(r3):"r"(a));
}
__device__ __forceinline__ void mmabf(float c[4],
    u32 a0,u32 a1,u32 a2,u32 a3,u32 b0,u32 b1){
    asm volatile("mma.sync.aligned.m16n8k16.row.col.f32.bf16.bf16.f32 "
        "{%0,%1,%2,%3},{%4,%5,%6,%7},{%8,%9},{%0,%1,%2,%3};"
        :"+f"(c[0]),"+f"(c[1]),"+f"(c[2]),"+f"(c[3])
        :"r"(a0),"r"(a1),"r"(a2),"r"(a3),"r"(b0),"r"(b1));
}
__device__ __forceinline__ u32 packbf(float x, float y){
    __nv_bfloat162 t = __floats2bfloat162_rn(x,y);
    return *reinterpret_cast<u32*>(&t);
}
__device__ __forceinline__ u32 split_pair(float v0, float v1, u32& lo){
    __nv_bfloat16 h0=__float2bfloat16(v0), h1=__float2bfloat16(v1);
    float l0 = v0-__bfloat162float(h0), l1 = v1-__bfloat162float(h1);
    lo = packbf(l0,l1);
    __nv_bfloat162 hh; hh.x=h0; hh.y=h1;
    return *reinterpret_cast<u32*>(&hh);
}
__device__ __forceinline__ void cpa16(u32 dst, const void* src){
    asm volatile("cp.async.cg.shared.global [%0],[%1],16;"::"r"(dst),"l"(src));
}
#define CPA_COMMIT() asm volatile("cp.async.commit_group;"::)
#define CPA_WAIT0()  asm volatile("cp.async.wait_group 0;"::)
#define CPA_WAIT1()  asm volatile("cp.async.wait_group 1;"::)

// padded-72 addressing (attention tiles)
template<int S>
__device__ __forceinline__ u32 a_addr(u32 base, int r0, int k0, int lane){
    int r = r0 + (lane&7) + ((lane>>3)&1)*8;
    int k = k0 + ((lane>>4)&1)*8;
    return base + (u32)(r*S + k)*2;
}
template<int S>
__device__ __forceinline__ u32 b_addr(u32 base, int n0, int k0, int lane){
    int n = n0 + (lane&7) + ((lane>>4)&1)*8;
    int k = k0 + ((lane>>3)&1)*8;
    return base + (u32)(n*S + k)*2;
}
template<int S>
__device__ __forceinline__ u32 bt_addr(u32 base, int n0, int k0, int lane){
    int k = k0 + (lane&7) + ((lane>>3)&1)*8;
    int n = n0 + ((lane>>4)&1)*8;
    return base + (u32)(k*S + n)*2;
}
// swizzled stride-32 addressing (GEMM tiles): phys chunk = c ^ ((row>>1)&3)
__device__ __forceinline__ u32 a_sw(u32 base, int r0, int k0, int lane){
    int r = r0 + (lane&7) + ((lane>>3)&1)*8;
    int c = (k0>>3) + ((lane>>4)&1);
    int ph = c ^ ((r>>1)&3);
    return base + (u32)(r*32 + ph*8)*2;
}
__device__ __forceinline__ u32 b_sw(u32 base, int n0, int k0, int lane){
    int n = n0 + (lane&7) + ((lane>>4)&1)*8;
    int c = (k0>>3) + ((lane>>3)&1);
    int ph = c ^ ((n>>1)&3);
    return base + (u32)(n*32 + ph*8)*2;
}

// ============================================================
// converts
// ============================================================
__global__ void __launch_bounds__(256) conv_split(
    const float* __restrict__ s, u16* __restrict__ h, u16* __restrict__ l, int n)
{
    int i = (blockIdx.x*256 + threadIdx.x)*8;
    if (i >= n) return;
    float4 x0 = *(const float4*)(s+i), x1 = *(const float4*)(s+i+4);
    float xs[8] = {x0.x,x0.y,x0.z,x0.w,x1.x,x1.y,x1.z,x1.w};
    u32 H[4], L[4];
    #pragma unroll
    for (int j=0;j<4;j++) H[j] = split_pair(xs[2*j], xs[2*j+1], L[j]);
    *(uint4*)(h+i) = make_uint4(H[0],H[1],H[2],H[3]);
    *(uint4*)(l+i) = make_uint4(L[0],L[1],L[2],L[3]);
}

struct WPack { const float* s[4]; u16* h[4]; u16* l[4]; };
__global__ void __launch_bounds__(256) conv_w4(WPack p)
{
    int w = blockIdx.y;
    const float* s = p.s[w];
    u16 *h = p.h[w], *l = p.l[w];
    int i = (blockIdx.x*256 + threadIdx.x)*8;
    float4 x0 = *(const float4*)(s+i), x1 = *(const float4*)(s+i+4);
    float xs[8] = {x0.x,x0.y,x0.z,x0.w,x1.x,x1.y,x1.z,x1.w};
    u32 H[4], L[4];
    #pragma unroll
    for (int j=0;j<4;j++) H[j] = split_pair(xs[2*j], xs[2*j+1], L[j]);
    *(uint4*)(h+i) = make_uint4(H[0],H[1],H[2],H[3]);
    *(uint4*)(l+i) = make_uint4(L[0],L[1],L[2],L[3]);
}

__global__ void __launch_bounds__(256) conv_split_t(
    const float* __restrict__ s, u16* __restrict__ h, u16* __restrict__ l)
{
    __shared__ float tile[32][33];
    int bx = blockIdx.x*32, by = blockIdx.y*32;
    int tx = threadIdx.x&31, ty = threadIdx.x>>5;
    for (int i = ty; i < 32; i += 8)
        tile[i][tx] = s[(size_t)(by+i)*DIMS + bx+tx];
    __syncthreads();
    for (int i = ty; i < 32; i += 8) {
        float v = tile[tx][i];
        __nv_bfloat16 hb = __float2bfloat16(v);
        h[(size_t)(bx+i)*DIMS + by+tx] = *(u16*)&hb;
        float lv = v - __bfloat162float(hb);
        __nv_bfloat16 lb = __float2bfloat16(lv);
        l[(size_t)(bx+i)*DIMS + by+tx] = *(u16*)&lb;
    }
}

__global__ void __launch_bounds__(256) bias2_k(
    const float* __restrict__ W, const float* __restrict__ b, float* __restrict__ out)
{
    int n = blockIdx.x*8 + (threadIdx.x>>5);
    int lane = threadIdx.x & 31;
    float s = 0.f;
    for (int k = lane; k < 1024; k += 32) s += b[k] * W[(size_t)n*1024 + k];
    #pragma unroll
    for (int o = 16; o; o >>= 1) s += __shfl_xor_sync(0xffffffffu, s, o);
    if (lane == 0) out[n] = s + b[n];
}

// ============================================================
// bf16x3 GEMM body: 128x128 tile, BK=32, 3-stage swizzled cp.async
// per-stage 32768 B: Ah@0 Al@8192 Bh@16384 Bl@24576
// ============================================================
template<bool F32OUT>
__device__ __forceinline__ void gemm_body(
    const u16* __restrict__ Agh, const u16* __restrict__ Agl,
    const u16* __restrict__ Bgh, const u16* __restrict__ Bgl,
    const float* __restrict__ bias,
    u16* __restrict__ Ch, u16* __restrict__ Cl,
    float* __restrict__ Cf, float* __restrict__ kc0,
    int row0, int col0, u16* smp)
{
    int t=threadIdx.x, warp=t>>5, lane=t&31;
    int wm=(warp>>2)*64, wn=(warp&3)*32;
    int gr=lane>>2, gq=lane&3;
    float acc[4][4][4]={};

    int lrow=t>>1, kc2=(t&1)*2;
    const u16* Ash = Agh + (size_t)(row0+lrow)*DIMS + kc2*8;
    const u16* Asl = Agl + (size_t)(row0+lrow)*DIMS + kc2*8;
    const u16* Bsh = Bgh + (size_t)(col0+lrow)*DIMS + kc2*8;
    const u16* Bsl = Bgl + (size_t)(col0+lrow)*DIMS + kc2*8;
    u32 base = smaddr(smp);
    int sw = (lrow>>1)&3;
    u32 d0 = base + (u32)(lrow*32 + (kc2^sw)*8)*2;
    u32 d1 = base + (u32)(lrow*32 + ((kc2+1)^sw)*8)*2;

    auto issue=[&](int it, int st){
        u32 o = (u32)st*32768;
        cpa16(d0+o,        Ash+it*32);  cpa16(d1+o,        Ash+it*32+8);
        cpa16(d0+o+8192,   Asl+it*32);  cpa16(d1+o+8192,   Asl+it*32+8);
        cpa16(d0+o+16384,  Bsh+it*32);  cpa16(d1+o+16384,  Bsh+it*32+8);
        cpa16(d0+o+24576,  Bsl+it*32);  cpa16(d1+o+24576,  Bsl+it*32+8);
        CPA_COMMIT();
    };
    issue(0,0); issue(1,1);

    for (int it=0; it<32; it++){
        int st = it - (it/3)*3;
        CPA_WAIT1();
        __syncthreads();
        if (it+2<32) issue(it+2, (it+2)-((it+2)/3)*3);
        u32 Ah = base + (u32)st*32768;
        u32 Al = Ah+8192, Bh = Ah+16384, Bl = Ah+24576;
        #pragma unroll
        for (int ksi=0;ksi<2;ksi++){
            int kk=ksi*16;
            u32 ah[4][4], al[4][4], bh2[4][2], bl2[4][2];
            #pragma unroll
            for (int m2=0;m2<4;m2++){
                ldsm4(ah[m2][0],ah[m2][1],ah[m2][2],ah[m2][3], a_sw(Ah, wm+m2*16, kk, lane));
                ldsm4(al[m2][0],al[m2][1],al[m2][2],al[m2][3], a_sw(Al, wm+m2*16, kk, lane));
            }
            #pragma unroll
            for (int pp=0;pp<2;pp++){
                u32 r0,r1,r2,r3;
                ldsm4(r0,r1,r2,r3, b_sw(Bh, wn+pp*16, kk, lane));
                bh2[2*pp][0]=r0; bh2[2*pp][1]=r1; bh2[2*pp+1][0]=r2; bh2[2*pp+1][1]=r3;
                ldsm4(r0,r1,r2,r3, b_sw(Bl, wn+pp*16, kk, lane));
                bl2[2*pp][0]=r0; bl2[2*pp][1]=r1; bl2[2*pp+1][0]=r2; bl2[2*pp+1][1]=r3;
            }
            #pragma unroll
            for (int m2=0;m2<4;m2++)
                #pragma unroll
                for (int na=0;na<4;na++){
                    mmabf(acc[m2][na], ah[m2][0],ah[m2][1],ah[m2][2],ah[m2][3], bh2[na][0],bh2[na][1]);
                    mmabf(acc[m2][na], ah[m2][0],ah[m2][1],ah[m2][2],ah[m2][3], bl2[na][0],bl2[na][1]);
                    mmabf(acc[m2][na], al[m2][0],al[m2][1],al[m2][2],al[m2][3], bh2[na][0],bh2[na][1]);
                }
        }
    }
    #pragma unroll
    for (int m2=0;m2<4;m2++)
        #pragma unroll
        for (int na=0;na<4;na++){
            int r  = row0+wm+m2*16+gr;
            int cn = col0+wn+na*8+2*gq;
            float b0v = bias? bias[cn]:0.f, b1v = bias? bias[cn+1]:0.f;
            float v0=acc[m2][na][0]+b0v, v1=acc[m2][na][1]+b1v;
            float v2=acc[m2][na][2]+b0v, v3=acc[m2][na][3]+b1v;
            if (F32OUT){
                *(float2*)(Cf+(size_t)r*DIMS+cn)     = make_float2(v0,v1);
                *(float2*)(Cf+(size_t)(r+8)*DIMS+cn) = make_float2(v2,v3);
            } else {
                u32 lo,hi;
                hi=split_pair(v0,v1,lo);
                *(u32*)(Ch+(size_t)r*DIMS+cn)=hi;  *(u32*)(Cl+(size_t)r*DIMS+cn)=lo;
                hi=split_pair(v2,v3,lo);
                *(u32*)(Ch+(size_t)(r+8)*DIMS+cn)=hi; *(u32*)(Cl+(size_t)(r+8)*DIMS+cn)=lo;
                if (kc0 && gq==0 && (((wn+na*8)&63)==0)){
                    int hh = cn>>6;
                    kc0[hh*MROWS + r]   = v0;
                    kc0[hh*MROWS + r+8] = v2;
                }
            }
        }
}

template<bool F32OUT>
__global__ void __launch_bounds__(256,2) gemm_one(
    const u16* Agh, const u16* Agl, const u16* Bgh, const u16* Bgl,
    const float* bias, u16* Ch, u16* Cl, float* Cf)
{
    extern __shared__ u16 smp[];
    gemm_body<F32OUT>(Agh,Agl,Bgh,Bgl,bias,Ch,Cl,Cf,nullptr,
                      blockIdx.y*128, blockIdx.x*128, smp);
}

__global__ void __launch_bounds__(256,2) gemm_qkv(
    const u16* xh, const u16* xl,
    const u16* wqh, const u16* wql, const u16* wkh, const u16* wkl,
    const u16* wvh, const u16* wvl,
    const float* bq, const float* bv,
    u16* qh, u16* ql, u16* kh, u16* kl, u16* vh, u16* vl, float* kc0)
{
    extern __shared__ u16 smp[];
    int z = blockIdx.z;
    const u16* Bh = (z==0)? wqh : (z==1)? wkh : wvh;
    const u16* Bl = (z==0)? wql : (z==1)? wkl : wvl;
    const float* bias = (z==0)? bq : (z==1)? nullptr : bv;
    u16* Ch = (z==0)? qh : (z==1)? kh : vh;
    u16* Cl = (z==0)? ql : (z==1)? kl : vl;
    float* kc = (z==1)? kc0 : nullptr;
    gemm_body<false>(xh,xl,Bh,Bl,bias,Ch,Cl,nullptr,kc,
                     blockIdx.y*128, blockIdx.x*128, smp);
}

// ============================================================
// Fused attention: logits + qk-spill + online softmax + PV, P in registers
// 128 q-rows x (b,h) per CTA, key chunks of 32, 1 syncthreads/chunk
// smem (u16 el): Qh 0..9216, Ql 9216.., KV base 18432 (buf: Kh,Kl,Vh,Vl 2304 each,
//   buf stride 9216), gz floats at el 36864 (2x32 f). Total 73984 B.
// ============================================================
__global__ void __launch_bounds__(256,2) attn_fused(
    const u16* __restrict__ qh_g, const u16* __restrict__ ql_g,
    const u16* __restrict__ kh_g, const u16* __restrict__ kl_g,
    const u16* __restrict__ vh_g, const u16* __restrict__ vl_g,
    const float* __restrict__ kc0, const float* __restrict__ factor,
    float* __restrict__ qk, u16* __restrict__ avh_g, u16* __restrict__ avl_g)
{
    extern __shared__ u16 sma[];
    u16 *Qh_p = sma, *Ql_p = sma+9216, *KV_p = sma+18432;
    float* gzb = (float*)(sma + 36864);

    int t=threadIdx.x, warp=t>>5, lane=t&31;
    int qb=blockIdx.x, bh=blockIdx.y, b=bh>>4, h=bh&15;
    int row0=qb*128, wm=warp*16;
    int gr=lane>>2, gq=lane&3;

    float zfac; { float f=*factor; zfac=fminf(fmaxf(log1pf(expf(f)),0.f),0.001f); }

    // stage Q (group 0 together with KV chunk 0)
    {
        int row=t>>1, half=(t&1)*32;
        const u16* sh = qh_g + (size_t)(b*CTX+row0+row)*DIMS + h*HD + half;
        const u16* sl = ql_g + (size_t)(b*CTX+row0+row)*DIMS + h*HD + half;
        u32 dh = smaddr(Qh_p) + (u32)(row*72+half)*2;
        u32 dl = smaddr(Ql_p) + (u32)(row*72+half)*2;
        #pragma unroll
        for (int c=0;c<32;c+=8){ cpa16(dh+c*2, sh+c); cpa16(dl+c*2, sl+c); }
    }
    int krow=t>>3, kseg=(t&7)*8;
    const float* kc0p = kc0 + h*MROWS + b*CTX;
    auto issue_kv=[&](int it, int buf){
        size_t g = (size_t)(b*CTX + it*32 + krow)*DIMS + h*HD + kseg;
        u32 d = smaddr(KV_p) + (u32)buf*18432 + (u32)(krow*72+kseg)*2;
        cpa16(d,        kh_g+g);
        cpa16(d+4608,   kl_g+g);
        cpa16(d+9216,   vh_g+g);
        cpa16(d+13824,  vl_g+g);
        if (t<8) cpa16(smaddr(gzb) + (u32)buf*128 + t*16, kc0p + it*32 + t*4);
        CPA_COMMIT();
    };
    issue_kv(0,0);

    float m0=-3.0e38f, m1=-3.0e38f, s0=0.f, s1=0.f;
    float acc_o[8][4]={};
    u32 qfh[4][4], qfl[4][4];
    float* Lb = qk + (size_t)bh*CTX*CTX;
    int rg0 = row0+wm+gr;

    for (int it=0; it<64; it++){
        int buf=it&1;
        u32 Kh = smaddr(KV_p) + (u32)buf*18432;
        u32 Kl = Kh+4608, Vh = Kh+9216, Vl = Kh+13824;
        CPA_WAIT0();
        __syncthreads();
        if (it==0){
            #pragma unroll
            for (int ks=0;ks<4;ks++){
                ldsm4(qfh[ks][0],qfh[ks][1],qfh[ks][2],qfh[ks][3], a_addr<72>(smaddr(Qh_p), wm, ks*16, lane));
                ldsm4(qfl[ks][0],qfl[ks][1],qfl[ks][2],qfl[ks][3], a_addr<72>(smaddr(Ql_p), wm, ks*16, lane));
            }
        }
        if (it+1<64) issue_kv(it+1, buf^1);

        // S = Q @ K^T  (16 rows x 32 keys per warp)
        float sacc[4][4]={};
        #pragma unroll
        for (int ks=0;ks<4;ks++){
            u32 bh2[4][2], bl2[4][2];
            #pragma unroll
            for (int pp=0;pp<2;pp++){
                u32 r0,r1,r2,r3;
                ldsm4(r0,r1,r2,r3, b_addr<72>(Kh, pp*16, ks*16, lane));
                bh2[2*pp][0]=r0; bh2[2*pp][1]=r1; bh2[2*pp+1][0]=r2; bh2[2*pp+1][1]=r3;
                ldsm4(r0,r1,r2,r3, b_addr<72>(Kl, pp*16, ks*16, lane));
                bl2[2*pp][0]=r0; bl2[2*pp][1]=r1; bl2[2*pp+1][0]=r2; bl2[2*pp+1][1]=r3;
            }
            #pragma unroll
            for (int na=0;na<4;na++){
                mmabf(sacc[na], qfh[ks][0],qfh[ks][1],qfh[ks][2],qfh[ks][3], bh2[na][0],bh2[na][1]);
                mmabf(sacc[na], qfh[ks][0],qfh[ks][1],qfh[ks][2],qfh[ks][3], bl2[na][0],bl2[na][1]);
                mmabf(sacc[na], qfl[ks][0],qfl[ks][1],qfl[ks][2],qfl[ks][3], bh2[na][0],bh2[na][1]);
            }
        }
        // gate + scale + spill qk + row max
        const float* gz = gzb + buf*32;
        float lm0=-3.0e38f, lm1=-3.0e38f;
        int kb = it*32;
        #pragma unroll
        for (int na=0;na<4;na++){
            int col=na*8+2*gq;
            float2 gv = *(const float2*)(gz + col);
            float z0 = ((gv.x==0.f)? zfac:1.f)*0.125f;
            float z1 = ((gv.y==0.f)? zfac:1.f)*0.125f;
            sacc[na][0]*=z0; sacc[na][1]*=z1; sacc[na][2]*=z0; sacc[na][3]*=z1;
            *(float2*)(Lb+(size_t)rg0*CTX+kb+col)     = make_float2(sacc[na][0],sacc[na][1]);
            *(float2*)(Lb+(size_t)(rg0+8)*CTX+kb+col) = make_float2(sacc[na][2],sacc[na][3]);
            lm0=fmaxf(lm0,fmaxf(sacc[na][0],sacc[na][1]));
            lm1=fmaxf(lm1,fmaxf(sacc[na][2],sacc[na][3]));
        }
        lm0=fmaxf(lm0,__shfl_xor_sync(0xffffffffu,lm0,1));
        lm0=fmaxf(lm0,__shfl_xor_sync(0xffffffffu,lm0,2));
        lm1=fmaxf(lm1,__shfl_xor_sync(0xffffffffu,lm1,1));
        lm1=fmaxf(lm1,__shfl_xor_sync(0xffffffffu,lm1,2));
        float mn0=fmaxf(m0,lm0), mn1=fmaxf(m1,lm1);
        float r0s=__expf(m0-mn0), r1s=__expf(m1-mn1);
        m0=mn0; m1=mn1; s0*=r0s; s1*=r1s;
        float ps0=0.f, ps1=0.f;
        #pragma unroll
        for (int na=0;na<4;na++){
            sacc[na][0]=__expf(sacc[na][0]-mn0); sacc[na][1]=__expf(sacc[na][1]-mn0);
            sacc[na][2]=__expf(sacc[na][2]-mn1); sacc[na][3]=__expf(sacc[na][3]-mn1);
            ps0+=sacc[na][0]+sacc[na][1]; ps1+=sacc[na][2]+sacc[na][3];
        }
        ps0+=__shfl_xor_sync(0xffffffffu,ps0,1); ps0+=__shfl_xor_sync(0xffffffffu,ps0,2);
        ps1+=__shfl_xor_sync(0xffffffffu,ps1,1); ps1+=__shfl_xor_sync(0xffffffffu,ps1,2);
        s0+=ps0; s1+=ps1;
        #pragma unroll
        for (int na=0;na<8;na++){
            acc_o[na][0]*=r0s; acc_o[na][1]*=r0s; acc_o[na][2]*=r1s; acc_o[na][3]*=r1s;
        }
        // PV: P from registers (S C-layout == PV A-layout)
        #pragma unroll
        for (int ks=0;ks<2;ks++){
            u32 pa[4], pl2[4];
            pa[0]=split_pair(sacc[2*ks][0],  sacc[2*ks][1],  pl2[0]);
            pa[1]=split_pair(sacc[2*ks][2],  sacc[2*ks][3],  pl2[1]);
            pa[2]=split_pair(sacc[2*ks+1][0],sacc[2*ks+1][1],pl2[2]);
            pa[3]=split_pair(sacc[2*ks+1][2],sacc[2*ks+1][3],pl2[3]);
            u32 bh2[8][2], bl2[8][2];
            #pragma unroll
            for (int pp=0;pp<4;pp++){
                u32 r0,r1,r2,r3;
                ldsm4t(r0,r1,r2,r3, bt_addr<72>(Vh, pp*16, ks*16, lane));
                bh2[2*pp][0]=r0; bh2[2*pp][1]=r1; bh2[2*pp+1][0]=r2; bh2[2*pp+1][1]=r3;
                ldsm4t(r0,r1,r2,r3, bt_addr<72>(Vl, pp*16, ks*16, lane));
                bl2[2*pp][0]=r0; bl2[2*pp][1]=r1; bl2[2*pp+1][0]=r2; bl2[2*pp+1][1]=r3;
            }
            #pragma unroll
            for (int na=0;na<8;na++){
                mmabf(acc_o[na], pa[0],pa[1],pa[2],pa[3], bh2[na][0],bh2[na][1]);
                mmabf(acc_o[na], pa[0],pa[1],pa[2],pa[3], bl2[na][0],bl2[na][1]);
                mmabf(acc_o[na], pl2[0],pl2[1],pl2[2],pl2[3], bh2[na][0],bh2[na][1]);
            }
        }
    }
    // epilogue
    float i0=1.f/s0, i1=1.f/s1;
    #pragma unroll
    for (int na=0;na<8;na++){
        int col=na*8+2*gq;
        size_t o0=(size_t)(b*CTX+rg0)*DIMS + h*HD + col;
        size_t o1=(size_t)(b*CTX+rg0+8)*DIMS + h*HD + col;
        u32 lo,hi;
        hi=split_pair(acc_o[na][0]*i0, acc_o[na][1]*i0, lo);
        *(u32*)(avh_g+o0)=hi; *(u32*)(avl_g+o0)=lo;
        hi=split_pair(acc_o[na][2]*i1, acc_o[na][3]*i1, lo);
        *(u32*)(avh_g+o1)=hi; *(u32*)(avl_g+o1)=lo;
    }
}

// ============================================================
extern "C" void kernel_launch(void* const* d_in, const int* in_sizes, int n_in,
                              void* d_out, int out_size)
{
    const float* x    = (const float*)d_in[0];
    const float* Wq   = (const float*)d_in[1];
    const float* bq   = (const float*)d_in[2];
    const float* Wk   = (const float*)d_in[3];
    const float* Wv   = (const float*)d_in[4];
    const float* bv   = (const float*)d_in[5];
    const float* Wout = (const float*)d_in[6];
    const float* bout = (const float*)d_in[7];
    const float* factor = (const float*)d_in[8];

    u16 *xh,*xl,*wqh,*wql,*wkh,*wkl,*wvh,*wvl,*woh,*wol,*wth,*wtl,*w2h,*w2l;
    u16 *qh,*ql,*kh,*kl,*vh,*vl,*avh,*avl;
    float *b2,*kc0,*qkfb;
    cudaGetSymbolAddress((void**)&xh,  g_xh);  cudaGetSymbolAddress((void**)&xl,  g_xl);
    cudaGetSymbolAddress((void**)&wqh, g_Wqh); cudaGetSymbolAddress((void**)&wql, g_Wql);
    cudaGetSymbolAddress((void**)&wkh, g_Wkh); cudaGetSymbolAddress((void**)&wkl, g_Wkl);
    cudaGetSymbolAddress((void**)&wvh, g_Wvh); cudaGetSymbolAddress((void**)&wvl, g_Wvl);
    cudaGetSymbolAddress((void**)&woh, g_Woh); cudaGetSymbolAddress((void**)&wol, g_Wol);
    cudaGetSymbolAddress((void**)&wth, g_Wth); cudaGetSymbolAddress((void**)&wtl, g_Wtl);
    cudaGetSymbolAddress((void**)&w2h, g_W2h); cudaGetSymbolAddress((void**)&w2l, g_W2l);
    cudaGetSymbolAddress((void**)&qh,  g_qh);  cudaGetSymbolAddress((void**)&ql,  g_ql);
    cudaGetSymbolAddress((void**)&kh,  g_kh);  cudaGetSymbolAddress((void**)&kl,  g_kl);
    cudaGetSymbolAddress((void**)&vh,  g_vh);  cudaGetSymbolAddress((void**)&vl,  g_vl);
    cudaGetSymbolAddress((void**)&avh, g_avh); cudaGetSymbolAddress((void**)&avl, g_avl);
    cudaGetSymbolAddress((void**)&b2,  g_b2);
    cudaGetSymbolAddress((void**)&kc0, g_kc0);
    cudaGetSymbolAddress((void**)&qkfb, g_qk_fallback);

    float* out = (float*)d_out;
    float* qkdst = ((size_t)out_size >= (size_t)OUT_ELEMS + QK_ELEMS)
                 ? (out + OUT_ELEMS) : qkfb;

    const int GSM = 98304, ASM = 73984;
    cudaFuncSetAttribute(gemm_qkv,       cudaFuncAttributeMaxDynamicSharedMemorySize, GSM);
    cudaFuncSetAttribute(gemm_one<false>,cudaFuncAttributeMaxDynamicSharedMemorySize, GSM);
    cudaFuncSetAttribute(gemm_one<true>, cudaFuncAttributeMaxDynamicSharedMemorySize, GSM);
    cudaFuncSetAttribute(attn_fused,     cudaFuncAttributeMaxDynamicSharedMemorySize, ASM);

    // converts
    conv_split<<<2048,256>>>(x, xh, xl, MROWS*DIMS);
    WPack wp;
    wp.s[0]=Wq;  wp.h[0]=wqh; wp.l[0]=wql;
    wp.s[1]=Wk;  wp.h[1]=wkh; wp.l[1]=wkl;
    wp.s[2]=Wv;  wp.h[2]=wvh; wp.l[2]=wvl;
    wp.s[3]=Wout;wp.h[3]=woh; wp.l[3]=wol;
    conv_w4<<<dim3(512,4),256>>>(wp);
    conv_split_t<<<dim3(32,32),256>>>(Wout, wth, wtl);
    bias2_k<<<128,256>>>(Wout, bout, b2);

    // W2 = Wout @ Wout
    gemm_one<false><<<dim3(8,8), 256, GSM>>>(woh, wol, wth, wtl, nullptr, w2h, w2l, nullptr);

    // fused QKV projections
    gemm_qkv<<<dim3(8,32,3), 256, GSM>>>(xh,xl, wqh,wql,wkh,wkl,wvh,wvl,
                                         bq,bv, qh,ql,kh,kl,vh,vl, kc0);

    // fused attention (spills qk)
    attn_fused<<<dim3(16,32), 256, ASM>>>(qh,ql,kh,kl,vh,vl, kc0, factor, qkdst, avh, avl);

    // out = wv @ W2^T + b2
    gemm_one<true><<<dim3(8,32), 256, GSM>>>(avh, avl, w2h, w2l, b2, nullptr, nullptr, out);
}